// round 5
// baseline (speedup 1.0000x reference)
#include <cuda_runtime.h>
#include <cuda_bf16.h>
#include <cstdint>
#include <math.h>

// Problem constants
#define BB 2
#define SS 4096
#define DD 768
#define HH 12
#define DHH 64
#define DFF 3072
#define MM (BB*SS)   // 8192

// ---------------------------------------------------------------------------
// Scratch (device globals — allocation-free per harness rules)
// ---------------------------------------------------------------------------
__device__ float g_l1[MM*DD];
__device__ float g_q [MM*DD];
__device__ float g_k [MM*DD];
__device__ float g_v [MM*DD];
__device__ float g_x1[MM*DD];
__device__ float g_l2[MM*DD];
__device__ float g_hb[MM*DFF];
// tf32-rounded weight copies (same layout as inputs, [K,N] row-major)
__device__ float g_wqr[DD*DD];
__device__ float g_wkr[DD*DD];
__device__ float g_wvr[DD*DD];
__device__ float g_w1r[DD*DFF];
__device__ float g_w2r[DFF*DD];

// ---------------------------------------------------------------------------
// Helpers
// ---------------------------------------------------------------------------
__device__ __forceinline__ float f2tf32(float x) {
    unsigned r;
    asm("cvt.rna.tf32.f32 %0, %1;" : "=r"(r) : "f"(x));
    return __uint_as_float(r);
}

__device__ __forceinline__ float ex2(float x) {
    float r;
    asm("ex2.approx.f32 %0, %1;" : "=f"(r) : "f"(x));
    return r;
}

__device__ __forceinline__ uint32_t smem_u32(const void* p) {
    uint32_t a;
    asm("{ .reg .u64 t; cvta.to.shared.u64 t, %1; cvt.u32.u64 %0, t; }"
        : "=r"(a) : "l"(p));
    return a;
}

#define CP_ASYNC16(dst, src) \
    asm volatile("cp.async.cg.shared.global [%0], [%1], 16;" :: "r"((uint32_t)(dst)), "l"(src) : "memory")
#define CP_ASYNC_COMMIT() asm volatile("cp.async.commit_group;" ::: "memory")
#define CP_ASYNC_WAIT(n)  asm volatile("cp.async.wait_group %0;" :: "n"(n) : "memory")

__device__ __forceinline__ void mma_tf32(float (&d)[4],
                                         unsigned a0, unsigned a1, unsigned a2, unsigned a3,
                                         unsigned b0, unsigned b1)
{
    asm volatile(
        "mma.sync.aligned.m16n8k8.row.col.f32.tf32.tf32.f32 "
        "{%0,%1,%2,%3}, {%4,%5,%6,%7}, {%8,%9}, {%0,%1,%2,%3};\n"
        : "+f"(d[0]), "+f"(d[1]), "+f"(d[2]), "+f"(d[3])
        : "r"(a0), "r"(a1), "r"(a2), "r"(a3), "r"(b0), "r"(b1));
}

// ---------------------------------------------------------------------------
// tf32 rounding pass for weights
// ---------------------------------------------------------------------------
__global__ void round_kernel(const float* __restrict__ in, float* __restrict__ out, int n4)
{
    int i = blockIdx.x * blockDim.x + threadIdx.x;
    if (i < n4) {
        float4 v = ((const float4*)in)[i];
        ((float4*)out)[i] = make_float4(f2tf32(v.x), f2tf32(v.y), f2tf32(v.z), f2tf32(v.w));
    }
}

// ---------------------------------------------------------------------------
// LayerNorm: torch-style, unbiased std (ddof=1), normalizer = (sigma + eps).
// 192 threads x float4. Output tf32-rounded.
// ---------------------------------------------------------------------------
__global__ void ln_kernel(const float* __restrict__ x,
                          const float* __restrict__ gamma,
                          const float* __restrict__ beta,
                          float* __restrict__ out)
{
    const int row = blockIdx.x;
    const int tid = threadIdx.x;
    const float* xr = x + (long)row * DD;

    float4 v = *(const float4*)(xr + tid * 4);
    float s  = v.x + v.y + v.z + v.w;
    float ss = v.x * v.x + v.y * v.y + v.z * v.z + v.w * v.w;
#pragma unroll
    for (int o = 16; o > 0; o >>= 1) {
        s  += __shfl_xor_sync(0xffffffffu, s,  o);
        ss += __shfl_xor_sync(0xffffffffu, ss, o);
    }
    __shared__ float sw[6], ssw[6];
    __shared__ float mu_s, inv_s;
    const int warp = tid >> 5, lane = tid & 31;
    if (lane == 0) { sw[warp] = s; ssw[warp] = ss; }
    __syncthreads();
    if (tid == 0) {
        float ts = 0.f, tss = 0.f;
#pragma unroll
        for (int i = 0; i < 6; i++) { ts += sw[i]; tss += ssw[i]; }
        float mu  = ts / 768.f;
        float var = fmaxf((tss - 768.f * mu * mu) / 767.f, 0.f);
        mu_s  = mu;
        inv_s = 1.f / (sqrtf(var) + 1e-6f);
    }
    __syncthreads();
    const float mu = mu_s, inv = inv_s;
    const float4 gm = *(const float4*)(gamma + tid * 4);
    const float4 bt = *(const float4*)(beta + tid * 4);
    *(float4*)(out + (long)row * DD + tid * 4) = make_float4(
        f2tf32(gm.x * (v.x - mu) * inv + bt.x),
        f2tf32(gm.y * (v.y - mu) * inv + bt.y),
        f2tf32(gm.z * (v.z - mu) * inv + bt.z),
        f2tf32(gm.w * (v.w - mu) * inv + bt.w));
}

// ---------------------------------------------------------------------------
// TF32 tensor-core GEMM, cp.async 2-stage, warp tile 64x64.
// C[M,N] = A[M,K] @ B[K,N] + bias. CTA tile 128x128, BK=32,
// 128 threads = 4 warps (2x2). A,B pre-rounded to tf32.
// EPI: 1 = bias+relu+round, 2 = bias+residual, 3 = bias+round
// ---------------------------------------------------------------------------
#define AP 36    // As pitch: frag banks (4g + t) distinct
#define BP 136   // Bs pitch: frag banks (8t + g) distinct
#define AS_FLOATS (128 * AP)          // per stage
#define BS_FLOATS (32 * BP)           // per stage
#define GEMM_SMEM ((2 * AS_FLOATS + 2 * BS_FLOATS) * 4)   // 71680 B

template<int EPI>
__global__ __launch_bounds__(128)
void mma_gemm(const float* __restrict__ A, const float* __restrict__ Bm,
              const float* __restrict__ bias, const float* __restrict__ res,
              float* __restrict__ C, int M, int N, int Kdim)
{
    extern __shared__ float gsm[];
    float* Asm = gsm;                       // [2][128*AP]
    float* Bsm = gsm + 2 * AS_FLOATS;       // [2][32*BP]

    const int tid  = threadIdx.x;
    const int wid  = tid >> 5, lane = tid & 31;
    const int wm   = wid >> 1, wn = wid & 1;       // 2x2 warp grid
    const int g    = lane >> 2, t = lane & 3;
    const int row0 = blockIdx.y * 128, col0 = blockIdx.x * 128;

    // staging: A row = tid (0..127), 32 cols; B row = tid>>2 (0..31), 32 cols
    const int ar = tid;
    const int br = tid >> 2, bc = (tid & 3) * 32;

    const float* Aptr = A  + (long)(row0 + ar) * Kdim;
    const float* Bptr = Bm + (long)br * N + col0 + bc;

    const uint32_t adst = smem_u32(Asm) + (ar * AP) * 4;
    const uint32_t bdst = smem_u32(Bsm) + (br * BP + bc) * 4;

    float acc[4][8][4];
#pragma unroll
    for (int i = 0; i < 4; i++)
#pragma unroll
        for (int j = 0; j < 8; j++)
#pragma unroll
            for (int k = 0; k < 4; k++) acc[i][j][k] = 0.f;

    const int niter = Kdim / 32;

    // prologue: stage 0
#pragma unroll
    for (int q = 0; q < 8; q++) CP_ASYNC16(adst + q * 16, Aptr + q * 4);
#pragma unroll
    for (int q = 0; q < 8; q++) CP_ASYNC16(bdst + q * 16, Bptr + q * 4);
    CP_ASYNC_COMMIT();

    for (int it = 0; it < niter; it++) {
        const int buf = it & 1;
        if (it + 1 < niter) {
            const int nb = (it + 1) & 1;
            const long ka = (long)(it + 1) * 32;
            const uint32_t ad = adst + nb * (AS_FLOATS * 4);
            const uint32_t bd = bdst + nb * (BS_FLOATS * 4);
#pragma unroll
            for (int q = 0; q < 8; q++) CP_ASYNC16(ad + q * 16, Aptr + ka + q * 4);
#pragma unroll
            for (int q = 0; q < 8; q++) CP_ASYNC16(bd + q * 16, Bptr + ka * N + q * 4);
            CP_ASYNC_COMMIT();
            CP_ASYNC_WAIT(1);
        } else {
            CP_ASYNC_WAIT(0);
        }
        __syncthreads();

        const float* as = Asm + buf * AS_FLOATS;
        const float* bs = Bsm + buf * BS_FLOATS;
#pragma unroll
        for (int ks = 0; ks < 4; ks++) {
            unsigned af[4][4];
#pragma unroll
            for (int mt = 0; mt < 4; mt++) {
                const int rb = (wm * 64 + mt * 16 + g) * AP + ks * 8 + t;
                af[mt][0] = __float_as_uint(as[rb]);
                af[mt][1] = __float_as_uint(as[rb + 8 * AP]);
                af[mt][2] = __float_as_uint(as[rb + 4]);
                af[mt][3] = __float_as_uint(as[rb + 8 * AP + 4]);
            }
            unsigned bf[8][2];
#pragma unroll
            for (int nt = 0; nt < 8; nt++) {
                const int cb = (ks * 8 + t) * BP + wn * 64 + nt * 8 + g;
                bf[nt][0] = __float_as_uint(bs[cb]);
                bf[nt][1] = __float_as_uint(bs[cb + 4 * BP]);
            }
#pragma unroll
            for (int mt = 0; mt < 4; mt++)
#pragma unroll
                for (int nt = 0; nt < 8; nt++)
                    mma_tf32(acc[mt][nt], af[mt][0], af[mt][1], af[mt][2], af[mt][3],
                             bf[nt][0], bf[nt][1]);
        }
        __syncthreads();
    }

    // epilogue
#pragma unroll
    for (int mt = 0; mt < 4; mt++) {
#pragma unroll
        for (int nt = 0; nt < 8; nt++) {
            const int  ccol = col0 + wn * 64 + nt * 8 + 2 * t;
            const long ra   = row0 + wm * 64 + mt * 16 + g;
            const long rb2  = ra + 8;
            const float bx = bias[ccol], by = bias[ccol + 1];
            float v0 = acc[mt][nt][0] + bx;
            float v1 = acc[mt][nt][1] + by;
            float v2 = acc[mt][nt][2] + bx;
            float v3 = acc[mt][nt][3] + by;
            if (EPI == 1) {
                v0 = f2tf32(fmaxf(v0, 0.f)); v1 = f2tf32(fmaxf(v1, 0.f));
                v2 = f2tf32(fmaxf(v2, 0.f)); v3 = f2tf32(fmaxf(v3, 0.f));
            }
            if (EPI == 3) {
                v0 = f2tf32(v0); v1 = f2tf32(v1);
                v2 = f2tf32(v2); v3 = f2tf32(v3);
            }
            if (EPI == 2) {
                const float2 r0 = *(const float2*)(res + ra  * N + ccol);
                const float2 r1 = *(const float2*)(res + rb2 * N + ccol);
                v0 += r0.x; v1 += r0.y; v2 += r1.x; v3 += r1.y;
            }
            *(float2*)(C + ra  * N + ccol) = make_float2(v0, v1);
            *(float2*)(C + rb2 * N + ccol) = make_float2(v2, v3);
        }
    }
}

// ---------------------------------------------------------------------------
// Flash attention, tf32 mma.sync. Q-tile 256 rows, 256 threads = 8 warps,
// warp w owns q rows 32w..32w+31 (two 16-row groups, mt=0,1). K-tile 64,
// double-buffered: K via cp.async, V via register prefetch + transpose.
// Grid x = head (fastest) for mask L2 reuse. Fuses residual: x1 = x + ctx.
// ---------------------------------------------------------------------------
#define PT 68
#define QT 256
#define KT 64
#define ATTN_SMEM ((QT + 2 * KT + 2 * KT + QT) * PT * (int)sizeof(float))  // 208896

__global__ __launch_bounds__(256, 1)
void attn_mma_kernel(const float* __restrict__ Q, const float* __restrict__ K,
                     const float* __restrict__ V, const float* __restrict__ mask,
                     const float* __restrict__ x, float* __restrict__ x1)
{
    extern __shared__ float sm[];
    float* Qs     = sm;                        // [256][PT]
    float* KsBase = sm + QT * PT;              // 2 x [64][PT]
    float* VtBase = sm + (QT + 2 * KT) * PT;   // 2 x [64][PT] (transposed)
    float* Ps     = sm + (QT + 4 * KT) * PT;   // [256][PT]

    const int tid = threadIdx.x;
    const int w = tid >> 5, lane = tid & 31;
    const int g = lane >> 2, t = lane & 3;
    const int h = blockIdx.x, qb = blockIdx.y, b = blockIdx.z;
    const int q0 = qb * QT, hoff = h * DHH;

    const float qscale = 0.125f * 1.4426950408889634f;  // 1/sqrt(64)*log2(e)

    // stage Q: one row per thread (scaled + rounded)
    {
        const float* qsrc = Q + ((long)(b * SS + q0 + tid)) * DD + hoff;
        float* qdst = &Qs[tid * PT];
#pragma unroll
        for (int i = 0; i < 64; i += 4) {
            float4 v = *(const float4*)(qsrc + i);
            *(float4*)(qdst + i) = make_float4(
                f2tf32(v.x * qscale), f2tf32(v.y * qscale),
                f2tf32(v.z * qscale), f2tf32(v.w * qscale));
        }
    }

    float o[2][8][4];
#pragma unroll
    for (int mt = 0; mt < 2; mt++)
#pragma unroll
        for (int nt = 0; nt < 8; nt++)
#pragma unroll
            for (int i = 0; i < 4; i++) o[mt][nt][i] = 0.f;
    float m_[2][2], l_[2][2];
#pragma unroll
    for (int mt = 0; mt < 2; mt++) {
        m_[mt][0] = -INFINITY; m_[mt][1] = -INFINITY;
        l_[mt][0] = 0.f;       l_[mt][1] = 0.f;
    }

    const float* mrow[2][2];
#pragma unroll
    for (int mt = 0; mt < 2; mt++) {
        const float* base = mask + ((long)b * SS + q0 + w * 32 + mt * 16 + g) * SS;
        mrow[mt][0] = base;
        mrow[mt][1] = base + 8L * SS;
    }

    // K/V staging mapping: kr = tid>>2 (0..63), cols kc..kc+15
    const int kr = tid >> 2, kc = (tid & 3) * 16;
    const uint32_t ksbase = smem_u32(KsBase);
    const uint32_t ksoff  = (kr * PT + kc) * 4;

    // prologue: stage kb=0
    float4 vreg[4];
    {
        const long kv = ((long)(b * SS + kr)) * DD + hoff + kc;
#pragma unroll
        for (int j = 0; j < 4; j++)
            CP_ASYNC16(ksbase + ksoff + j * 16, K + kv + j * 4);
        CP_ASYNC_COMMIT();
#pragma unroll
        for (int j = 0; j < 4; j++)
            vreg[j] = *(const float4*)(V + kv + j * 4);
        CP_ASYNC_WAIT(0);
#pragma unroll
        for (int j = 0; j < 4; j++) {
            VtBase[(kc + j * 4 + 0) * PT + kr] = vreg[j].x;
            VtBase[(kc + j * 4 + 1) * PT + kr] = vreg[j].y;
            VtBase[(kc + j * 4 + 2) * PT + kr] = vreg[j].z;
            VtBase[(kc + j * 4 + 3) * PT + kr] = vreg[j].w;
        }
    }
    __syncthreads();

    const int NKB = SS / KT;   // 64
    for (int kb = 0; kb < NKB; kb++) {
        const int cur = kb & 1, nxt = cur ^ 1;
        const int k0 = kb * KT;
        const bool more = (kb + 1 < NKB);

        if (more) {
            const long kv = ((long)(b * SS + k0 + KT + kr)) * DD + hoff + kc;
            const uint32_t kd = ksbase + nxt * (KT * PT * 4) + ksoff;
#pragma unroll
            for (int j = 0; j < 4; j++)
                CP_ASYNC16(kd + j * 16, K + kv + j * 4);
            CP_ASYNC_COMMIT();
#pragma unroll
            for (int j = 0; j < 4; j++)
                vreg[j] = *(const float4*)(V + kv + j * 4);
        }

        const float* Ks = KsBase + cur * KT * PT;
        const float* Vt = VtBase + cur * KT * PT;

        // S = Qs @ Ks^T (per warp: 32 q rows x 64 keys)
        float s[2][8][4];
#pragma unroll
        for (int mt = 0; mt < 2; mt++)
#pragma unroll
            for (int nt = 0; nt < 8; nt++)
#pragma unroll
                for (int i = 0; i < 4; i++) s[mt][nt][i] = 0.f;
#pragma unroll
        for (int ks = 0; ks < 8; ks++) {
            unsigned af[2][4];
#pragma unroll
            for (int mt = 0; mt < 2; mt++) {
                const int rb = (w * 32 + mt * 16 + g) * PT + ks * 8 + t;
                af[mt][0] = __float_as_uint(Qs[rb]);
                af[mt][1] = __float_as_uint(Qs[rb + 8 * PT]);
                af[mt][2] = __float_as_uint(Qs[rb + 4]);
                af[mt][3] = __float_as_uint(Qs[rb + 8 * PT + 4]);
            }
#pragma unroll
            for (int nt = 0; nt < 8; nt++) {
                const int cb = (nt * 8 + g) * PT + ks * 8 + t;
                unsigned b0 = __float_as_uint(Ks[cb]);
                unsigned b1 = __float_as_uint(Ks[cb + 4]);
#pragma unroll
                for (int mt = 0; mt < 2; mt++)
                    mma_tf32(s[mt][nt], af[mt][0], af[mt][1], af[mt][2], af[mt][3], b0, b1);
            }
        }

        // mask + streaming softmax (log2 domain), per 16-row group
#pragma unroll
        for (int mt = 0; mt < 2; mt++) {
            float mx_a = -INFINITY, mx_b = -INFINITY;
#pragma unroll
            for (int nt = 0; nt < 8; nt++) {
                const float2 ma = *(const float2*)(mrow[mt][0] + k0 + nt * 8 + 2 * t);
                const float2 mb = *(const float2*)(mrow[mt][1] + k0 + nt * 8 + 2 * t);
                s[mt][nt][0] *= ma.x; s[mt][nt][1] *= ma.y;
                s[mt][nt][2] *= mb.x; s[mt][nt][3] *= mb.y;
                mx_a = fmaxf(mx_a, fmaxf(s[mt][nt][0], s[mt][nt][1]));
                mx_b = fmaxf(mx_b, fmaxf(s[mt][nt][2], s[mt][nt][3]));
            }
            mx_a = fmaxf(mx_a, __shfl_xor_sync(0xffffffffu, mx_a, 1));
            mx_a = fmaxf(mx_a, __shfl_xor_sync(0xffffffffu, mx_a, 2));
            mx_b = fmaxf(mx_b, __shfl_xor_sync(0xffffffffu, mx_b, 1));
            mx_b = fmaxf(mx_b, __shfl_xor_sync(0xffffffffu, mx_b, 2));
            const float mn_a = fmaxf(m_[mt][0], mx_a), mn_b = fmaxf(m_[mt][1], mx_b);
            const float al_a = ex2(m_[mt][0] - mn_a), al_b = ex2(m_[mt][1] - mn_b);
            float sum_a = 0.f, sum_b = 0.f;
#pragma unroll
            for (int nt = 0; nt < 8; nt++) {
                const float p0 = ex2(s[mt][nt][0] - mn_a);
                const float p1 = ex2(s[mt][nt][1] - mn_a);
                const float p2 = ex2(s[mt][nt][2] - mn_b);
                const float p3 = ex2(s[mt][nt][3] - mn_b);
                sum_a += p0 + p1; sum_b += p2 + p3;
                const int pb = (w * 32 + mt * 16 + g) * PT + nt * 8 + 2 * t;
                *(float2*)&Ps[pb] = make_float2(f2tf32(p0), f2tf32(p1));
                *(float2*)&Ps[pb + 8 * PT] = make_float2(f2tf32(p2), f2tf32(p3));
            }
            sum_a += __shfl_xor_sync(0xffffffffu, sum_a, 1);
            sum_a += __shfl_xor_sync(0xffffffffu, sum_a, 2);
            sum_b += __shfl_xor_sync(0xffffffffu, sum_b, 1);
            sum_b += __shfl_xor_sync(0xffffffffu, sum_b, 2);
            l_[mt][0] = l_[mt][0] * al_a + sum_a;
            l_[mt][1] = l_[mt][1] * al_b + sum_b;
            m_[mt][0] = mn_a; m_[mt][1] = mn_b;
#pragma unroll
            for (int nt = 0; nt < 8; nt++) {
                o[mt][nt][0] *= al_a; o[mt][nt][1] *= al_a;
                o[mt][nt][2] *= al_b; o[mt][nt][3] *= al_b;
            }
        }
        __syncwarp();

        // O += P @ V
#pragma unroll
        for (int ks = 0; ks < 8; ks++) {
            unsigned af[2][4];
#pragma unroll
            for (int mt = 0; mt < 2; mt++) {
                const int rb = (w * 32 + mt * 16 + g) * PT + ks * 8 + t;
                af[mt][0] = __float_as_uint(Ps[rb]);
                af[mt][1] = __float_as_uint(Ps[rb + 8 * PT]);
                af[mt][2] = __float_as_uint(Ps[rb + 4]);
                af[mt][3] = __float_as_uint(Ps[rb + 8 * PT + 4]);
            }
#pragma unroll
            for (int nt = 0; nt < 8; nt++) {
                const int cb = (nt * 8 + g) * PT + ks * 8 + t;
                unsigned b0 = __float_as_uint(Vt[cb]);
                unsigned b1 = __float_as_uint(Vt[cb + 4]);
#pragma unroll
                for (int mt = 0; mt < 2; mt++)
                    mma_tf32(o[mt][nt], af[mt][0], af[mt][1], af[mt][2], af[mt][3], b0, b1);
            }
        }

        if (more) {
            CP_ASYNC_WAIT(0);
            float* vt = VtBase + nxt * KT * PT;
#pragma unroll
            for (int j = 0; j < 4; j++) {
                vt[(kc + j * 4 + 0) * PT + kr] = vreg[j].x;
                vt[(kc + j * 4 + 1) * PT + kr] = vreg[j].y;
                vt[(kc + j * 4 + 2) * PT + kr] = vreg[j].z;
                vt[(kc + j * 4 + 3) * PT + kr] = vreg[j].w;
            }
        }
        __syncthreads();
    }

    // finalize + fused residual: x1 = x + O / l
#pragma unroll
    for (int mt = 0; mt < 2; mt++) {
        const float inv_a = 1.f / l_[mt][0], inv_b = 1.f / l_[mt][1];
        const long oa = ((long)(b * SS + q0 + w * 32 + mt * 16 + g)) * DD + hoff;
        const long ob = oa + 8L * DD;
#pragma unroll
        for (int nt = 0; nt < 8; nt++) {
            const int c = nt * 8 + 2 * t;
            const float2 xa = *(const float2*)(x + oa + c);
            const float2 xb = *(const float2*)(x + ob + c);
            *(float2*)(x1 + oa + c) = make_float2(xa.x + o[mt][nt][0] * inv_a,
                                                  xa.y + o[mt][nt][1] * inv_a);
            *(float2*)(x1 + ob + c) = make_float2(xb.x + o[mt][nt][2] * inv_b,
                                                  xb.y + o[mt][nt][3] * inv_b);
        }
    }
}

// ---------------------------------------------------------------------------
// Launch
// ---------------------------------------------------------------------------
extern "C" void kernel_launch(void* const* d_in, const int* in_sizes, int n_in,
                              void* d_out, int out_size)
{
    const float* x    = (const float*)d_in[0];
    const float* mask = (const float*)d_in[1];
    const float* wq   = (const float*)d_in[2];
    const float* bq   = (const float*)d_in[3];
    const float* wk   = (const float*)d_in[4];
    const float* bk   = (const float*)d_in[5];
    const float* wv   = (const float*)d_in[6];
    const float* bv   = (const float*)d_in[7];
    // d_in[8]=wo, d_in[9]=bo unused by the reference forward
    const float* w1   = (const float*)d_in[10];
    const float* b1   = (const float*)d_in[11];
    const float* w2   = (const float*)d_in[12];
    const float* b2   = (const float*)d_in[13];
    const float* g1   = (const float*)d_in[14];
    const float* be1  = (const float*)d_in[15];
    const float* g2   = (const float*)d_in[16];
    const float* be2  = (const float*)d_in[17];
    float* out = (float*)d_out;

    float *l1, *qb_, *kb_, *vb_, *x1, *l2, *hb;
    float *wqr, *wkr, *wvr, *w1r, *w2r;
    cudaGetSymbolAddress((void**)&l1, g_l1);
    cudaGetSymbolAddress((void**)&qb_, g_q);
    cudaGetSymbolAddress((void**)&kb_, g_k);
    cudaGetSymbolAddress((void**)&vb_, g_v);
    cudaGetSymbolAddress((void**)&x1, g_x1);
    cudaGetSymbolAddress((void**)&l2, g_l2);
    cudaGetSymbolAddress((void**)&hb, g_hb);
    cudaGetSymbolAddress((void**)&wqr, g_wqr);
    cudaGetSymbolAddress((void**)&wkr, g_wkr);
    cudaGetSymbolAddress((void**)&wvr, g_wvr);
    cudaGetSymbolAddress((void**)&w1r, g_w1r);
    cudaGetSymbolAddress((void**)&w2r, g_w2r);

    cudaFuncSetAttribute(mma_gemm<1>, cudaFuncAttributeMaxDynamicSharedMemorySize, GEMM_SMEM);
    cudaFuncSetAttribute(mma_gemm<2>, cudaFuncAttributeMaxDynamicSharedMemorySize, GEMM_SMEM);
    cudaFuncSetAttribute(mma_gemm<3>, cudaFuncAttributeMaxDynamicSharedMemorySize, GEMM_SMEM);
    cudaFuncSetAttribute(attn_mma_kernel, cudaFuncAttributeMaxDynamicSharedMemorySize, ATTN_SMEM);

    // tf32-round the weights once (layout unchanged)
    const int ndd4  = DD * DD / 4;
    const int nff4  = DD * DFF / 4;
    round_kernel<<<(ndd4 + 255) / 256, 256>>>(wq, wqr, ndd4);
    round_kernel<<<(ndd4 + 255) / 256, 256>>>(wk, wkr, ndd4);
    round_kernel<<<(ndd4 + 255) / 256, 256>>>(wv, wvr, ndd4);
    round_kernel<<<(nff4 + 255) / 256, 256>>>(w1, w1r, nff4);
    round_kernel<<<(nff4 + 255) / 256, 256>>>(w2, w2r, nff4);

    // LN1 (rounds output)
    ln_kernel<<<MM, 192>>>(x, g1, be1, l1);

    // QKV projections (EPI=3: bias + tf32 round)
    dim3 gproj(DD / 128, MM / 128);   // (6, 64)
    mma_gemm<3><<<gproj, 128, GEMM_SMEM>>>(l1, wqr, bq, nullptr, qb_, MM, DD, DD);
    mma_gemm<3><<<gproj, 128, GEMM_SMEM>>>(l1, wkr, bk, nullptr, kb_, MM, DD, DD);
    mma_gemm<3><<<gproj, 128, GEMM_SMEM>>>(l1, wvr, bv, nullptr, vb_, MM, DD, DD);

    // Flash attention + residual; head = fastest grid dim for mask L2 reuse
    attn_mma_kernel<<<dim3(HH, SS / QT, BB), 256, ATTN_SMEM>>>(qb_, kb_, vb_, mask, x, x1);

    // LN2 (rounds output)
    ln_kernel<<<MM, 192>>>(x1, g2, be2, l2);

    // FFN
    mma_gemm<1><<<dim3(DFF / 128, MM / 128), 128, GEMM_SMEM>>>(l2, w1r, b1, nullptr, hb, MM, DFF, DD);
    mma_gemm<2><<<dim3(DD / 128, MM / 128), 128, GEMM_SMEM>>>(hb, w2r, b2, x1, out, MM, DD, DFF);
}

// round 6
// speedup vs baseline: 1.0553x; 1.0553x over previous
#include <cuda_runtime.h>
#include <cuda_bf16.h>
#include <cstdint>
#include <math.h>

// Problem constants
#define BB 2
#define SS 4096
#define DD 768
#define HH 12
#define DHH 64
#define DFF 3072
#define MM (BB*SS)   // 8192

// ---------------------------------------------------------------------------
// Scratch (device globals — allocation-free per harness rules)
// ---------------------------------------------------------------------------
__device__ float g_l1[MM*DD];
__device__ float g_q [MM*DD];
__device__ float g_k [MM*DD];
__device__ float g_v [MM*DD];
__device__ float g_x1[MM*DD];
__device__ float g_l2[MM*DD];
__device__ float g_hb[MM*DFF];
// tf32-rounded weight copies (same layout as inputs)
__device__ float g_wqr[DD*DD];
__device__ float g_wkr[DD*DD];
__device__ float g_wvr[DD*DD];
__device__ float g_w1r[DD*DFF];
__device__ float g_w2r[DFF*DD];

// ---------------------------------------------------------------------------
// Helpers
// ---------------------------------------------------------------------------
__device__ __forceinline__ float f2tf32(float x) {
    unsigned r;
    asm("cvt.rna.tf32.f32 %0, %1;" : "=r"(r) : "f"(x));
    return __uint_as_float(r);
}

__device__ __forceinline__ float ex2(float x) {
    float r;
    asm("ex2.approx.f32 %0, %1;" : "=f"(r) : "f"(x));
    return r;
}

__device__ __forceinline__ uint32_t smem_u32(const void* p) {
    uint32_t a;
    asm("{ .reg .u64 t; cvta.to.shared.u64 t, %1; cvt.u32.u64 %0, t; }"
        : "=r"(a) : "l"(p));
    return a;
}

#define CP_ASYNC16(dst, src) \
    asm volatile("cp.async.cg.shared.global [%0], [%1], 16;" :: "r"((uint32_t)(dst)), "l"(src) : "memory")
#define CP_ASYNC_COMMIT() asm volatile("cp.async.commit_group;" ::: "memory")
#define CP_ASYNC_WAIT(n)  asm volatile("cp.async.wait_group %0;" :: "n"(n) : "memory")

__device__ __forceinline__ void mma_tf32(float (&d)[4],
                                         unsigned a0, unsigned a1, unsigned a2, unsigned a3,
                                         unsigned b0, unsigned b1)
{
    asm volatile(
        "mma.sync.aligned.m16n8k8.row.col.f32.tf32.tf32.f32 "
        "{%0,%1,%2,%3}, {%4,%5,%6,%7}, {%8,%9}, {%0,%1,%2,%3};\n"
        : "+f"(d[0]), "+f"(d[1]), "+f"(d[2]), "+f"(d[3])
        : "r"(a0), "r"(a1), "r"(a2), "r"(a3), "r"(b0), "r"(b1));
}

// ---------------------------------------------------------------------------
// Single tf32 rounding pass over all 5 weight tensors (one launch)
// ---------------------------------------------------------------------------
#define DD4  (DD * DD / 4)     // 147456
#define FF4  (DD * DFF / 4)    // 589824
#define TOT4 (3 * DD4 + 2 * FF4)

__global__ void round_all_kernel(const float* __restrict__ wq, float* __restrict__ oq,
                                 const float* __restrict__ wk, float* __restrict__ ok,
                                 const float* __restrict__ wv, float* __restrict__ ov,
                                 const float* __restrict__ w1, float* __restrict__ o1,
                                 const float* __restrict__ w2, float* __restrict__ o2)
{
    long i = (long)blockIdx.x * blockDim.x + threadIdx.x;
    if (i >= TOT4) return;
    const float4* in; float4* out; long off;
    if      (i < DD4)              { in = (const float4*)wq; out = (float4*)oq; off = i; }
    else if (i < 2 * DD4)          { in = (const float4*)wk; out = (float4*)ok; off = i - DD4; }
    else if (i < 3 * DD4)          { in = (const float4*)wv; out = (float4*)ov; off = i - 2 * DD4; }
    else if (i < 3 * DD4 + FF4)    { in = (const float4*)w1; out = (float4*)o1; off = i - 3 * DD4; }
    else                           { in = (const float4*)w2; out = (float4*)o2; off = i - 3 * DD4 - FF4; }
    float4 v = in[off];
    out[off] = make_float4(f2tf32(v.x), f2tf32(v.y), f2tf32(v.z), f2tf32(v.w));
}

// ---------------------------------------------------------------------------
// LayerNorm: torch-style, unbiased std (ddof=1), normalizer = (sigma + eps).
// 192 threads x float4. Output tf32-rounded.
// ---------------------------------------------------------------------------
__global__ void ln_kernel(const float* __restrict__ x,
                          const float* __restrict__ gamma,
                          const float* __restrict__ beta,
                          float* __restrict__ out)
{
    const int row = blockIdx.x;
    const int tid = threadIdx.x;
    const float* xr = x + (long)row * DD;

    float4 v = *(const float4*)(xr + tid * 4);
    float s  = v.x + v.y + v.z + v.w;
    float ss = v.x * v.x + v.y * v.y + v.z * v.z + v.w * v.w;
#pragma unroll
    for (int o = 16; o > 0; o >>= 1) {
        s  += __shfl_xor_sync(0xffffffffu, s,  o);
        ss += __shfl_xor_sync(0xffffffffu, ss, o);
    }
    __shared__ float sw[6], ssw[6];
    __shared__ float mu_s, inv_s;
    const int warp = tid >> 5, lane = tid & 31;
    if (lane == 0) { sw[warp] = s; ssw[warp] = ss; }
    __syncthreads();
    if (tid == 0) {
        float ts = 0.f, tss = 0.f;
#pragma unroll
        for (int i = 0; i < 6; i++) { ts += sw[i]; tss += ssw[i]; }
        float mu  = ts / 768.f;
        float var = fmaxf((tss - 768.f * mu * mu) / 767.f, 0.f);
        mu_s  = mu;
        inv_s = 1.f / (sqrtf(var) + 1e-6f);
    }
    __syncthreads();
    const float mu = mu_s, inv = inv_s;
    const float4 gm = *(const float4*)(gamma + tid * 4);
    const float4 bt = *(const float4*)(beta + tid * 4);
    *(float4*)(out + (long)row * DD + tid * 4) = make_float4(
        f2tf32(gm.x * (v.x - mu) * inv + bt.x),
        f2tf32(gm.y * (v.y - mu) * inv + bt.y),
        f2tf32(gm.z * (v.z - mu) * inv + bt.z),
        f2tf32(gm.w * (v.w - mu) * inv + bt.w));
}

// ---------------------------------------------------------------------------
// TF32 tensor-core GEMM, 3-stage cp.async pipeline, one sync per K-iter.
// C[M,N] = A[M,K] @ B[K,N] + bias. CTA tile 128x128, BK=16,
// 256 threads = 8 warps (2x4), warp tile 64x32. A,B pre-rounded tf32.
// EPI: 1 = bias+relu+round, 2 = bias+residual, 3 = bias+round
// ---------------------------------------------------------------------------
#define AP 20    // As pitch: frag banks (4g + t) distinct
#define BP 136   // Bs pitch: frag banks (8t + g) distinct
#define ASF (128 * AP)    // floats per A stage (2560)
#define BSF (16 * BP)     // floats per B stage (2176)
#define GEMM_SMEM (3 * (ASF + BSF) * 4)   // 56832 B

template<int EPI>
__global__ __launch_bounds__(256, 2)
void mma_gemm(const float* __restrict__ A, const float* __restrict__ Bm,
              const float* __restrict__ bias, const float* __restrict__ res,
              float* __restrict__ C, int M, int N, int Kdim)
{
    extern __shared__ float gsm[];
    float* Asm = gsm;                 // 3 stages of [128*AP]
    float* Bsm = gsm + 3 * ASF;       // 3 stages of [16*BP]

    const int tid  = threadIdx.x;
    const int wid  = tid >> 5, lane = tid & 31;
    const int wm   = wid >> 2, wn = wid & 3;
    const int g    = lane >> 2, t = lane & 3;
    const int row0 = blockIdx.y * 128, col0 = blockIdx.x * 128;

    const int ar = tid >> 1, ac = (tid & 1) * 8;
    const int br = tid >> 4, bc = (tid & 15) * 8;

    const float* Aptr = A  + (long)(row0 + ar) * Kdim + ac;
    const float* Bptr = Bm + (long)br * N + col0 + bc;

    const uint32_t adst = smem_u32(Asm) + (ar * AP + ac) * 4;
    const uint32_t bdst = smem_u32(Bsm) + (br * BP + bc) * 4;

    float acc[4][4][4];
#pragma unroll
    for (int i = 0; i < 4; i++)
#pragma unroll
        for (int j = 0; j < 4; j++)
#pragma unroll
            for (int k = 0; k < 4; k++) acc[i][j][k] = 0.f;

    const int niter = Kdim / 16;

    // prologue: stages 0 and 1
#pragma unroll
    for (int p = 0; p < 2; p++) {
        const long ka = (long)p * 16;
        const uint32_t ad = adst + p * (ASF * 4);
        const uint32_t bd = bdst + p * (BSF * 4);
        CP_ASYNC16(ad, Aptr + ka);
        CP_ASYNC16(ad + 16, Aptr + ka + 4);
        CP_ASYNC16(bd, Bptr + ka * N);
        CP_ASYNC16(bd + 16, Bptr + ka * N + 4);
        CP_ASYNC_COMMIT();
    }

    int slot = 0, nslot = 2;   // slot = it%3; nslot = (it+2)%3
    for (int it = 0; it < niter; it++) {
        if (it + 1 < niter) { CP_ASYNC_WAIT(1); } else { CP_ASYNC_WAIT(0); }
        __syncthreads();

        if (it + 2 < niter) {
            const long ka = (long)(it + 2) * 16;
            const uint32_t ad = adst + nslot * (ASF * 4);
            const uint32_t bd = bdst + nslot * (BSF * 4);
            CP_ASYNC16(ad, Aptr + ka);
            CP_ASYNC16(ad + 16, Aptr + ka + 4);
            CP_ASYNC16(bd, Bptr + ka * N);
            CP_ASYNC16(bd + 16, Bptr + ka * N + 4);
            CP_ASYNC_COMMIT();
        }

        const float* as = Asm + slot * ASF;
        const float* bs = Bsm + slot * BSF;
#pragma unroll
        for (int ks = 0; ks < 2; ks++) {
            unsigned af[4][4];
#pragma unroll
            for (int mt = 0; mt < 4; mt++) {
                const int rb = (wm * 64 + mt * 16 + g) * AP + ks * 8 + t;
                af[mt][0] = __float_as_uint(as[rb]);
                af[mt][1] = __float_as_uint(as[rb + 8 * AP]);
                af[mt][2] = __float_as_uint(as[rb + 4]);
                af[mt][3] = __float_as_uint(as[rb + 8 * AP + 4]);
            }
            unsigned bf[4][2];
#pragma unroll
            for (int nt = 0; nt < 4; nt++) {
                const int cb = (ks * 8 + t) * BP + wn * 32 + nt * 8 + g;
                bf[nt][0] = __float_as_uint(bs[cb]);
                bf[nt][1] = __float_as_uint(bs[cb + 4 * BP]);
            }
#pragma unroll
            for (int mt = 0; mt < 4; mt++)
#pragma unroll
                for (int nt = 0; nt < 4; nt++)
                    mma_tf32(acc[mt][nt], af[mt][0], af[mt][1], af[mt][2], af[mt][3],
                             bf[nt][0], bf[nt][1]);
        }
        slot = (slot == 2) ? 0 : slot + 1;
        nslot = (nslot == 2) ? 0 : nslot + 1;
    }

    // epilogue
#pragma unroll
    for (int mt = 0; mt < 4; mt++) {
#pragma unroll
        for (int nt = 0; nt < 4; nt++) {
            const int  ccol = col0 + wn * 32 + nt * 8 + 2 * t;
            const long ra   = row0 + wm * 64 + mt * 16 + g;
            const long rb2  = ra + 8;
            const float bx = bias[ccol], by = bias[ccol + 1];
            float v0 = acc[mt][nt][0] + bx;
            float v1 = acc[mt][nt][1] + by;
            float v2 = acc[mt][nt][2] + bx;
            float v3 = acc[mt][nt][3] + by;
            if (EPI == 1) {
                v0 = f2tf32(fmaxf(v0, 0.f)); v1 = f2tf32(fmaxf(v1, 0.f));
                v2 = f2tf32(fmaxf(v2, 0.f)); v3 = f2tf32(fmaxf(v3, 0.f));
            }
            if (EPI == 3) {
                v0 = f2tf32(v0); v1 = f2tf32(v1);
                v2 = f2tf32(v2); v3 = f2tf32(v3);
            }
            if (EPI == 2) {
                const float2 r0 = *(const float2*)(res + ra  * N + ccol);
                const float2 r1 = *(const float2*)(res + rb2 * N + ccol);
                v0 += r0.x; v1 += r0.y; v2 += r1.x; v3 += r1.y;
            }
            *(float2*)(C + ra  * N + ccol) = make_float2(v0, v1);
            *(float2*)(C + rb2 * N + ccol) = make_float2(v2, v3);
        }
    }
}

// ---------------------------------------------------------------------------
// Flash attention, tf32 mma.sync. Q-tile 128 rows, 256 threads = 8 warps
// (warp w owns q rows 16w..16w+15). Q lives in REGISTERS (staged via Ps,
// warp-private rows -> no block sync). K double-buffered via cp.async,
// V double-buffered via register prefetch + smem transpose. One
// __syncthreads per k-iter. smem 104448 B -> 2 CTAs/SM.
// Grid x = head (fastest) for mask L2 reuse. Fuses residual: x1 = x + ctx.
// ---------------------------------------------------------------------------
#define PT 68
#define QT 128
#define KT 64
// smem: Ks 2x[64][PT], Vt 2x[64][PT], Ps [128][PT]
#define ATTN_SMEM ((4 * KT + QT) * PT * (int)sizeof(float))   // 104448

__global__ __launch_bounds__(256, 2)
void attn_mma_kernel(const float* __restrict__ Q, const float* __restrict__ K,
                     const float* __restrict__ V, const float* __restrict__ mask,
                     const float* __restrict__ x, float* __restrict__ x1)
{
    extern __shared__ float sm[];
    float* KsBase = sm;                   // 2 x [64][PT]
    float* VtBase = sm + 2 * KT * PT;     // 2 x [64][PT] (transposed)
    float* Ps     = sm + 4 * KT * PT;     // [128][PT]

    const int tid = threadIdx.x;
    const int w = tid >> 5, lane = tid & 31;
    const int g = lane >> 2, t = lane & 3;
    const int h = blockIdx.x, qb = blockIdx.y, b = blockIdx.z;
    const int q0 = qb * QT, hoff = h * DHH;

    const float qscale = 0.125f * 1.4426950408889634f;  // 1/sqrt(64)*log2(e)

    // stage Q through Ps (warp-private rows: warp w stages rows 16w..16w+15),
    // then pull fragments into registers. Only warp-level sync needed.
    unsigned qf[8][4];
    {
        const int sr = tid >> 1, sc0 = (tid & 1) * 32;   // sr in [16w,16w+15]
        const float* qsrc = Q + ((long)(b * SS + q0 + sr)) * DD + hoff + sc0;
        float* qdst = &Ps[sr * PT + sc0];
#pragma unroll
        for (int i = 0; i < 32; i += 4) {
            float4 v = *(const float4*)(qsrc + i);
            *(float4*)(qdst + i) = make_float4(
                f2tf32(v.x * qscale), f2tf32(v.y * qscale),
                f2tf32(v.z * qscale), f2tf32(v.w * qscale));
        }
        __syncwarp();
#pragma unroll
        for (int ks = 0; ks < 8; ks++) {
            const int rb = (w * 16 + g) * PT + ks * 8 + t;
            qf[ks][0] = __float_as_uint(Ps[rb]);
            qf[ks][1] = __float_as_uint(Ps[rb + 8 * PT]);
            qf[ks][2] = __float_as_uint(Ps[rb + 4]);
            qf[ks][3] = __float_as_uint(Ps[rb + 8 * PT + 4]);
        }
        __syncwarp();
    }

    float o[8][4];
#pragma unroll
    for (int nt = 0; nt < 8; nt++)
#pragma unroll
        for (int i = 0; i < 4; i++) o[nt][i] = 0.f;
    float m_a = -INFINITY, m_b = -INFINITY, l_a = 0.f, l_b = 0.f;

    const float* mrow_a = mask + ((long)b * SS + q0 + w * 16 + g) * SS;
    const float* mrow_b = mrow_a + 8L * SS;

    // K/V staging mapping: kr = tid>>2 (0..63), cols kc..kc+15
    const int kr = tid >> 2, kc = (tid & 3) * 16;
    const uint32_t ksbase = smem_u32(KsBase);
    const uint32_t ksoff  = (kr * PT + kc) * 4;

    // prologue: stage kb=0 into slot 0
    float4 vreg[4];
    {
        const long kv = ((long)(b * SS + kr)) * DD + hoff + kc;
#pragma unroll
        for (int j = 0; j < 4; j++)
            CP_ASYNC16(ksbase + ksoff + j * 16, K + kv + j * 4);
        CP_ASYNC_COMMIT();
#pragma unroll
        for (int j = 0; j < 4; j++)
            vreg[j] = *(const float4*)(V + kv + j * 4);
#pragma unroll
        for (int j = 0; j < 4; j++) {
            VtBase[(kc + j * 4 + 0) * PT + kr] = vreg[j].x;
            VtBase[(kc + j * 4 + 1) * PT + kr] = vreg[j].y;
            VtBase[(kc + j * 4 + 2) * PT + kr] = vreg[j].z;
            VtBase[(kc + j * 4 + 3) * PT + kr] = vreg[j].w;
        }
        CP_ASYNC_WAIT(0);
    }
    __syncthreads();

    const int NKB = SS / KT;   // 64
    for (int kb = 0; kb < NKB; kb++) {
        const int cur = kb & 1, nxt = cur ^ 1;
        const int k0 = kb * KT;
        const bool more = (kb + 1 < NKB);

        // prefetch next K (cp.async) and next V (registers)
        if (more) {
            const long kv = ((long)(b * SS + k0 + KT + kr)) * DD + hoff + kc;
            const uint32_t kd = ksbase + nxt * (KT * PT * 4) + ksoff;
#pragma unroll
            for (int j = 0; j < 4; j++)
                CP_ASYNC16(kd + j * 16, K + kv + j * 4);
            CP_ASYNC_COMMIT();
#pragma unroll
            for (int j = 0; j < 4; j++)
                vreg[j] = *(const float4*)(V + kv + j * 4);
        }

        const float* Ks = KsBase + cur * KT * PT;
        const float* Vt = VtBase + cur * KT * PT;

        // S = Q @ Ks^T (Q in registers)
        float s[8][4];
#pragma unroll
        for (int nt = 0; nt < 8; nt++)
#pragma unroll
            for (int i = 0; i < 4; i++) s[nt][i] = 0.f;
#pragma unroll
        for (int ks = 0; ks < 8; ks++) {
#pragma unroll
            for (int nt = 0; nt < 8; nt++) {
                const int cb = (nt * 8 + g) * PT + ks * 8 + t;
                unsigned b0 = __float_as_uint(Ks[cb]);
                unsigned b1 = __float_as_uint(Ks[cb + 4]);
                mma_tf32(s[nt], qf[ks][0], qf[ks][1], qf[ks][2], qf[ks][3], b0, b1);
            }
        }

        // multiplicative mask then streaming softmax (log2 domain)
        float mx_a = -INFINITY, mx_b = -INFINITY;
#pragma unroll
        for (int nt = 0; nt < 8; nt++) {
            const float2 ma = *(const float2*)(mrow_a + k0 + nt * 8 + 2 * t);
            const float2 mb = *(const float2*)(mrow_b + k0 + nt * 8 + 2 * t);
            s[nt][0] *= ma.x; s[nt][1] *= ma.y;
            s[nt][2] *= mb.x; s[nt][3] *= mb.y;
            mx_a = fmaxf(mx_a, fmaxf(s[nt][0], s[nt][1]));
            mx_b = fmaxf(mx_b, fmaxf(s[nt][2], s[nt][3]));
        }
        mx_a = fmaxf(mx_a, __shfl_xor_sync(0xffffffffu, mx_a, 1));
        mx_a = fmaxf(mx_a, __shfl_xor_sync(0xffffffffu, mx_a, 2));
        mx_b = fmaxf(mx_b, __shfl_xor_sync(0xffffffffu, mx_b, 1));
        mx_b = fmaxf(mx_b, __shfl_xor_sync(0xffffffffu, mx_b, 2));
        const float mn_a = fmaxf(m_a, mx_a), mn_b = fmaxf(m_b, mx_b);
        const float al_a = ex2(m_a - mn_a), al_b = ex2(m_b - mn_b);
        float sum_a = 0.f, sum_b = 0.f;
#pragma unroll
        for (int nt = 0; nt < 8; nt++) {
            const float p0 = ex2(s[nt][0] - mn_a);
            const float p1 = ex2(s[nt][1] - mn_a);
            const float p2 = ex2(s[nt][2] - mn_b);
            const float p3 = ex2(s[nt][3] - mn_b);
            sum_a += p0 + p1; sum_b += p2 + p3;
            const int pb = (w * 16 + g) * PT + nt * 8 + 2 * t;
            *(float2*)&Ps[pb] = make_float2(f2tf32(p0), f2tf32(p1));
            *(float2*)&Ps[pb + 8 * PT] = make_float2(f2tf32(p2), f2tf32(p3));
        }
        sum_a += __shfl_xor_sync(0xffffffffu, sum_a, 1);
        sum_a += __shfl_xor_sync(0xffffffffu, sum_a, 2);
        sum_b += __shfl_xor_sync(0xffffffffu, sum_b, 1);
        sum_b += __shfl_xor_sync(0xffffffffu, sum_b, 2);
        l_a = l_a * al_a + sum_a;
        l_b = l_b * al_b + sum_b;
        m_a = mn_a; m_b = mn_b;
#pragma unroll
        for (int nt = 0; nt < 8; nt++) {
            o[nt][0] *= al_a; o[nt][1] *= al_a;
            o[nt][2] *= al_b; o[nt][3] *= al_b;
        }
        __syncwarp();   // Ps rows are warp-private

        // O += P @ V
#pragma unroll
        for (int ks = 0; ks < 8; ks++) {
            const int rb = (w * 16 + g) * PT + ks * 8 + t;
            unsigned a0 = __float_as_uint(Ps[rb]);
            unsigned a1 = __float_as_uint(Ps[rb + 8 * PT]);
            unsigned a2 = __float_as_uint(Ps[rb + 4]);
            unsigned a3 = __float_as_uint(Ps[rb + 8 * PT + 4]);
#pragma unroll
            for (int nt = 0; nt < 8; nt++) {
                const int cb = (nt * 8 + g) * PT + ks * 8 + t;
                unsigned b0 = __float_as_uint(Vt[cb]);
                unsigned b1 = __float_as_uint(Vt[cb + 4]);
                mma_tf32(o[nt], a0, a1, a2, a3, b0, b1);
            }
        }

        // finish next-stage staging: wait K, write Vt(nxt) from registers
        if (more) {
            CP_ASYNC_WAIT(0);
            float* vt = VtBase + nxt * KT * PT;
#pragma unroll
            for (int j = 0; j < 4; j++) {
                vt[(kc + j * 4 + 0) * PT + kr] = vreg[j].x;
                vt[(kc + j * 4 + 1) * PT + kr] = vreg[j].y;
                vt[(kc + j * 4 + 2) * PT + kr] = vreg[j].z;
                vt[(kc + j * 4 + 3) * PT + kr] = vreg[j].w;
            }
        }
        __syncthreads();
    }

    // finalize + fused residual: x1 = x + O / l
    const float inv_a = 1.f / l_a, inv_b = 1.f / l_b;
    const long oa = ((long)(b * SS + q0 + w * 16 + g)) * DD + hoff;
    const long ob = oa + 8L * DD;
#pragma unroll
    for (int nt = 0; nt < 8; nt++) {
        const int c = nt * 8 + 2 * t;
        const float2 xa = *(const float2*)(x + oa + c);
        const float2 xb = *(const float2*)(x + ob + c);
        *(float2*)(x1 + oa + c) = make_float2(xa.x + o[nt][0] * inv_a,
                                              xa.y + o[nt][1] * inv_a);
        *(float2*)(x1 + ob + c) = make_float2(xb.x + o[nt][2] * inv_b,
                                              xb.y + o[nt][3] * inv_b);
    }
}

// ---------------------------------------------------------------------------
// Launch
// ---------------------------------------------------------------------------
extern "C" void kernel_launch(void* const* d_in, const int* in_sizes, int n_in,
                              void* d_out, int out_size)
{
    const float* x    = (const float*)d_in[0];
    const float* mask = (const float*)d_in[1];
    const float* wq   = (const float*)d_in[2];
    const float* bq   = (const float*)d_in[3];
    const float* wk   = (const float*)d_in[4];
    const float* bk   = (const float*)d_in[5];
    const float* wv   = (const float*)d_in[6];
    const float* bv   = (const float*)d_in[7];
    // d_in[8]=wo, d_in[9]=bo unused by the reference forward
    const float* w1   = (const float*)d_in[10];
    const float* b1   = (const float*)d_in[11];
    const float* w2   = (const float*)d_in[12];
    const float* b2   = (const float*)d_in[13];
    const float* g1   = (const float*)d_in[14];
    const float* be1  = (const float*)d_in[15];
    const float* g2   = (const float*)d_in[16];
    const float* be2  = (const float*)d_in[17];
    float* out = (float*)d_out;

    float *l1, *qb_, *kb_, *vb_, *x1, *l2, *hb;
    float *wqr, *wkr, *wvr, *w1r, *w2r;
    cudaGetSymbolAddress((void**)&l1, g_l1);
    cudaGetSymbolAddress((void**)&qb_, g_q);
    cudaGetSymbolAddress((void**)&kb_, g_k);
    cudaGetSymbolAddress((void**)&vb_, g_v);
    cudaGetSymbolAddress((void**)&x1, g_x1);
    cudaGetSymbolAddress((void**)&l2, g_l2);
    cudaGetSymbolAddress((void**)&hb, g_hb);
    cudaGetSymbolAddress((void**)&wqr, g_wqr);
    cudaGetSymbolAddress((void**)&wkr, g_wkr);
    cudaGetSymbolAddress((void**)&wvr, g_wvr);
    cudaGetSymbolAddress((void**)&w1r, g_w1r);
    cudaGetSymbolAddress((void**)&w2r, g_w2r);

    cudaFuncSetAttribute(mma_gemm<1>, cudaFuncAttributeMaxDynamicSharedMemorySize, GEMM_SMEM);
    cudaFuncSetAttribute(mma_gemm<2>, cudaFuncAttributeMaxDynamicSharedMemorySize, GEMM_SMEM);
    cudaFuncSetAttribute(mma_gemm<3>, cudaFuncAttributeMaxDynamicSharedMemorySize, GEMM_SMEM);
    cudaFuncSetAttribute(attn_mma_kernel, cudaFuncAttributeMaxDynamicSharedMemorySize, ATTN_SMEM);

    // tf32-round all weights in ONE launch
    round_all_kernel<<<(TOT4 + 255) / 256, 256>>>(wq, wqr, wk, wkr, wv, wvr,
                                                  w1, w1r, w2, w2r);

    // LN1 (rounds output)
    ln_kernel<<<MM, 192>>>(x, g1, be1, l1);

    // QKV projections (EPI=3: bias + tf32 round)
    dim3 gproj(DD / 128, MM / 128);   // (6, 64)
    mma_gemm<3><<<gproj, 256, GEMM_SMEM>>>(l1, wqr, bq, nullptr, qb_, MM, DD, DD);
    mma_gemm<3><<<gproj, 256, GEMM_SMEM>>>(l1, wkr, bk, nullptr, kb_, MM, DD, DD);
    mma_gemm<3><<<gproj, 256, GEMM_SMEM>>>(l1, wvr, bv, nullptr, vb_, MM, DD, DD);

    // Flash attention + residual; head = fastest grid dim for mask L2 reuse
    attn_mma_kernel<<<dim3(HH, SS / QT, BB), 256, ATTN_SMEM>>>(qb_, kb_, vb_, mask, x, x1);

    // LN2 (rounds output)
    ln_kernel<<<MM, 192>>>(x1, g2, be2, l2);

    // FFN
    mma_gemm<1><<<dim3(DFF / 128, MM / 128), 256, GEMM_SMEM>>>(l2, w1r, b1, nullptr, hb, MM, DFF, DD);
    mma_gemm<2><<<dim3(DD / 128, MM / 128), 256, GEMM_SMEM>>>(hb, w2r, b2, x1, out, MM, DD, DFF);
}

// round 7
// speedup vs baseline: 1.0824x; 1.0257x over previous
#include <cuda_runtime.h>
#include <cuda_bf16.h>
#include <cstdint>
#include <math.h>

// Problem constants
#define BB 2
#define SS 4096
#define DD 768
#define HH 12
#define DHH 64
#define DFF 3072
#define MM (BB*SS)    // 8192
#define QKVN (3*DD)   // 2304

// ---------------------------------------------------------------------------
// Scratch (device globals — allocation-free per harness rules)
// ---------------------------------------------------------------------------
__device__ float g_l1[MM*DD];
__device__ float g_qkv[MM*QKVN];     // fused Q|K|V output
__device__ float g_x1[MM*DD];
__device__ float g_l2[MM*DD];
__device__ float g_hb[MM*DFF];
__device__ float g_wqkv[DD*QKVN];    // concat rounded [768][2304]
__device__ float g_bqkv[QKVN];
__device__ float g_w1r[DD*DFF];
__device__ float g_w2r[DFF*DD];

// ---------------------------------------------------------------------------
// Helpers
// ---------------------------------------------------------------------------
__device__ __forceinline__ float f2tf32(float x) {
    unsigned r;
    asm("cvt.rna.tf32.f32 %0, %1;" : "=r"(r) : "f"(x));
    return __uint_as_float(r);
}

__device__ __forceinline__ float ex2(float x) {
    float r;
    asm("ex2.approx.f32 %0, %1;" : "=f"(r) : "f"(x));
    return r;
}

__device__ __forceinline__ uint32_t smem_u32(const void* p) {
    uint32_t a;
    asm("{ .reg .u64 t; cvta.to.shared.u64 t, %1; cvt.u32.u64 %0, t; }"
        : "=r"(a) : "l"(p));
    return a;
}

#define CP_ASYNC16(dst, src) \
    asm volatile("cp.async.cg.shared.global [%0], [%1], 16;" :: "r"((uint32_t)(dst)), "l"(src) : "memory")
#define CP_ASYNC_COMMIT() asm volatile("cp.async.commit_group;" ::: "memory")
#define CP_ASYNC_WAIT(n)  asm volatile("cp.async.wait_group %0;" :: "n"(n) : "memory")

__device__ __forceinline__ void mma_tf32(float (&d)[4],
                                         unsigned a0, unsigned a1, unsigned a2, unsigned a3,
                                         unsigned b0, unsigned b1)
{
    asm volatile(
        "mma.sync.aligned.m16n8k8.row.col.f32.tf32.tf32.f32 "
        "{%0,%1,%2,%3}, {%4,%5,%6,%7}, {%8,%9}, {%0,%1,%2,%3};\n"
        : "+f"(d[0]), "+f"(d[1]), "+f"(d[2]), "+f"(d[3])
        : "r"(a0), "r"(a1), "r"(a2), "r"(a3), "r"(b0), "r"(b1));
}

// ---------------------------------------------------------------------------
// One-pass weight prep: round wq/wk/wv into fused [768][2304], round w1, w2.
// Also concatenates biases (raw copy) into g_bqkv.
// ---------------------------------------------------------------------------
#define DD4  (DD * DD / 4)     // 147456
#define FF4  (DD * DFF / 4)    // 589824
#define TOT4 (3 * DD4 + 2 * FF4)
#define ROW4 (DD / 4)          // 192 float4 per weight row
#define QROW4 (QKVN / 4)       // 576 float4 per fused row

__global__ void prep_kernel(const float* __restrict__ wq, const float* __restrict__ wk,
                            const float* __restrict__ wv, float* __restrict__ wqkv,
                            const float* __restrict__ bq, const float* __restrict__ bk,
                            const float* __restrict__ bv, float* __restrict__ bqkv,
                            const float* __restrict__ w1, float* __restrict__ o1,
                            const float* __restrict__ w2, float* __restrict__ o2)
{
    long i = (long)blockIdx.x * blockDim.x + threadIdx.x;
    if (i >= TOT4) return;

    if (i < QROW4) {   // bias concat (raw fp32; added in fp32 epilogue)
        const float* bsrc = (i < ROW4) ? (bq + i * 4)
                          : (i < 2 * ROW4) ? (bk + (i - ROW4) * 4)
                          : (bv + (i - 2 * ROW4) * 4);
        ((float4*)bqkv)[i] = *(const float4*)bsrc;
    }

    float4 v;
    if (i < 3 * DD4) {
        const int sel   = (int)(i / DD4);          // 0=q,1=k,2=v
        const long loc  = i - (long)sel * DD4;
        const long r    = loc / ROW4;
        const long c4   = loc % ROW4;
        const float4* in = (sel == 0) ? (const float4*)wq
                         : (sel == 1) ? (const float4*)wk : (const float4*)wv;
        v = in[loc];
        ((float4*)wqkv)[r * QROW4 + sel * ROW4 + c4] =
            make_float4(f2tf32(v.x), f2tf32(v.y), f2tf32(v.z), f2tf32(v.w));
    } else if (i < 3 * DD4 + FF4) {
        const long off = i - 3 * DD4;
        v = ((const float4*)w1)[off];
        ((float4*)o1)[off] = make_float4(f2tf32(v.x), f2tf32(v.y), f2tf32(v.z), f2tf32(v.w));
    } else {
        const long off = i - 3 * DD4 - FF4;
        v = ((const float4*)w2)[off];
        ((float4*)o2)[off] = make_float4(f2tf32(v.x), f2tf32(v.y), f2tf32(v.z), f2tf32(v.w));
    }
}

// ---------------------------------------------------------------------------
// LayerNorm: torch-style, unbiased std (ddof=1), normalizer = (sigma + eps).
// 192 threads x float4. Output tf32-rounded.
// ---------------------------------------------------------------------------
__global__ void ln_kernel(const float* __restrict__ x,
                          const float* __restrict__ gamma,
                          const float* __restrict__ beta,
                          float* __restrict__ out)
{
    const int row = blockIdx.x;
    const int tid = threadIdx.x;
    const float* xr = x + (long)row * DD;

    float4 v = *(const float4*)(xr + tid * 4);
    float s  = v.x + v.y + v.z + v.w;
    float ss = v.x * v.x + v.y * v.y + v.z * v.z + v.w * v.w;
#pragma unroll
    for (int o = 16; o > 0; o >>= 1) {
        s  += __shfl_xor_sync(0xffffffffu, s,  o);
        ss += __shfl_xor_sync(0xffffffffu, ss, o);
    }
    __shared__ float sw[6], ssw[6];
    __shared__ float mu_s, inv_s;
    const int warp = tid >> 5, lane = tid & 31;
    if (lane == 0) { sw[warp] = s; ssw[warp] = ss; }
    __syncthreads();
    if (tid == 0) {
        float ts = 0.f, tss = 0.f;
#pragma unroll
        for (int i = 0; i < 6; i++) { ts += sw[i]; tss += ssw[i]; }
        float mu  = ts / 768.f;
        float var = fmaxf((tss - 768.f * mu * mu) / 767.f, 0.f);
        mu_s  = mu;
        inv_s = 1.f / (sqrtf(var) + 1e-6f);
    }
    __syncthreads();
    const float mu = mu_s, inv = inv_s;
    const float4 gm = *(const float4*)(gamma + tid * 4);
    const float4 bt = *(const float4*)(beta + tid * 4);
    *(float4*)(out + (long)row * DD + tid * 4) = make_float4(
        f2tf32(gm.x * (v.x - mu) * inv + bt.x),
        f2tf32(gm.y * (v.y - mu) * inv + bt.y),
        f2tf32(gm.z * (v.z - mu) * inv + bt.z),
        f2tf32(gm.w * (v.w - mu) * inv + bt.w));
}

// ---------------------------------------------------------------------------
// TF32 tensor-core GEMM, 4-stage cp.async pipeline, one sync per K-iter.
// C[M,N] = A[M,K] @ B[K,N] + bias. CTA tile 128x128, BK=16,
// 256 threads = 8 warps (2x4), warp tile 64x32. A,B pre-rounded tf32.
// EPI: 1 = bias+relu+round, 2 = bias+residual, 3 = bias+round
// ---------------------------------------------------------------------------
#define AP 20    // As pitch: frag banks (4g + t) distinct
#define BP 136   // Bs pitch: frag banks (8t + g) distinct
#define ASF (128 * AP)    // floats per A stage (2560)
#define BSF (16 * BP)     // floats per B stage (2176)
#define NSTG 4
#define GEMM_SMEM (NSTG * (ASF + BSF) * 4)   // 75776 B

template<int EPI>
__global__ __launch_bounds__(256, 2)
void mma_gemm(const float* __restrict__ A, const float* __restrict__ Bm,
              const float* __restrict__ bias, const float* __restrict__ res,
              float* __restrict__ C, int M, int N, int Kdim)
{
    extern __shared__ float gsm[];
    float* Asm = gsm;                    // NSTG stages of [128*AP]
    float* Bsm = gsm + NSTG * ASF;       // NSTG stages of [16*BP]

    const int tid  = threadIdx.x;
    const int wid  = tid >> 5, lane = tid & 31;
    const int wm   = wid >> 2, wn = wid & 3;
    const int g    = lane >> 2, t = lane & 3;
    const int row0 = blockIdx.y * 128, col0 = blockIdx.x * 128;

    const int ar = tid >> 1, ac = (tid & 1) * 8;
    const int br = tid >> 4, bc = (tid & 15) * 8;

    const float* Aptr = A  + (long)(row0 + ar) * Kdim + ac;
    const float* Bptr = Bm + (long)br * N + col0 + bc;

    const uint32_t adst = smem_u32(Asm) + (ar * AP + ac) * 4;
    const uint32_t bdst = smem_u32(Bsm) + (br * BP + bc) * 4;

    float acc[4][4][4];
#pragma unroll
    for (int i = 0; i < 4; i++)
#pragma unroll
        for (int j = 0; j < 4; j++)
#pragma unroll
            for (int k = 0; k < 4; k++) acc[i][j][k] = 0.f;

    const int niter = Kdim / 16;

    // prologue: stages 0..2
#pragma unroll
    for (int p = 0; p < 3; p++) {
        const long ka = (long)p * 16;
        const uint32_t ad = adst + p * (ASF * 4);
        const uint32_t bd = bdst + p * (BSF * 4);
        CP_ASYNC16(ad, Aptr + ka);
        CP_ASYNC16(ad + 16, Aptr + ka + 4);
        CP_ASYNC16(bd, Bptr + ka * N);
        CP_ASYNC16(bd + 16, Bptr + ka * N + 4);
        CP_ASYNC_COMMIT();
    }

    for (int it = 0; it < niter; it++) {
        if (it + 2 < niter)      { CP_ASYNC_WAIT(2); }
        else if (it + 1 < niter) { CP_ASYNC_WAIT(1); }
        else                     { CP_ASYNC_WAIT(0); }
        __syncthreads();

        if (it + 3 < niter) {
            const int ns = (it + 3) & (NSTG - 1);
            const long ka = (long)(it + 3) * 16;
            const uint32_t ad = adst + ns * (ASF * 4);
            const uint32_t bd = bdst + ns * (BSF * 4);
            CP_ASYNC16(ad, Aptr + ka);
            CP_ASYNC16(ad + 16, Aptr + ka + 4);
            CP_ASYNC16(bd, Bptr + ka * N);
            CP_ASYNC16(bd + 16, Bptr + ka * N + 4);
            CP_ASYNC_COMMIT();
        }

        const int slot = it & (NSTG - 1);
        const float* as = Asm + slot * ASF;
        const float* bs = Bsm + slot * BSF;
#pragma unroll
        for (int ks = 0; ks < 2; ks++) {
            unsigned af[4][4];
#pragma unroll
            for (int mt = 0; mt < 4; mt++) {
                const int rb = (wm * 64 + mt * 16 + g) * AP + ks * 8 + t;
                af[mt][0] = __float_as_uint(as[rb]);
                af[mt][1] = __float_as_uint(as[rb + 8 * AP]);
                af[mt][2] = __float_as_uint(as[rb + 4]);
                af[mt][3] = __float_as_uint(as[rb + 8 * AP + 4]);
            }
            unsigned bf[4][2];
#pragma unroll
            for (int nt = 0; nt < 4; nt++) {
                const int cb = (ks * 8 + t) * BP + wn * 32 + nt * 8 + g;
                bf[nt][0] = __float_as_uint(bs[cb]);
                bf[nt][1] = __float_as_uint(bs[cb + 4 * BP]);
            }
#pragma unroll
            for (int mt = 0; mt < 4; mt++)
#pragma unroll
                for (int nt = 0; nt < 4; nt++)
                    mma_tf32(acc[mt][nt], af[mt][0], af[mt][1], af[mt][2], af[mt][3],
                             bf[nt][0], bf[nt][1]);
        }
    }

    // epilogue
#pragma unroll
    for (int mt = 0; mt < 4; mt++) {
#pragma unroll
        for (int nt = 0; nt < 4; nt++) {
            const int  ccol = col0 + wn * 32 + nt * 8 + 2 * t;
            const long ra   = row0 + wm * 64 + mt * 16 + g;
            const long rb2  = ra + 8;
            const float bx = bias[ccol], by = bias[ccol + 1];
            float v0 = acc[mt][nt][0] + bx;
            float v1 = acc[mt][nt][1] + by;
            float v2 = acc[mt][nt][2] + bx;
            float v3 = acc[mt][nt][3] + by;
            if (EPI == 1) {
                v0 = f2tf32(fmaxf(v0, 0.f)); v1 = f2tf32(fmaxf(v1, 0.f));
                v2 = f2tf32(fmaxf(v2, 0.f)); v3 = f2tf32(fmaxf(v3, 0.f));
            }
            if (EPI == 3) {
                v0 = f2tf32(v0); v1 = f2tf32(v1);
                v2 = f2tf32(v2); v3 = f2tf32(v3);
            }
            if (EPI == 2) {
                const float2 r0 = *(const float2*)(res + ra  * N + ccol);
                const float2 r1 = *(const float2*)(res + rb2 * N + ccol);
                v0 += r0.x; v1 += r0.y; v2 += r1.x; v3 += r1.y;
            }
            *(float2*)(C + ra  * N + ccol) = make_float2(v0, v1);
            *(float2*)(C + rb2 * N + ccol) = make_float2(v2, v3);
        }
    }
}

// ---------------------------------------------------------------------------
// Flash attention over fused QKV buffer [M][2304] (Q|K|V, tf32-rounded).
// Q-tile 128 rows, 256 threads = 8 warps (warp w owns q rows 16w..16w+15).
// Q in registers; K double-buffered via cp.async; V double-buffered via
// register prefetch + smem transpose. One __syncthreads per k-iter.
// P/Q fed to MMA without explicit tf32 cvt (HW truncates).
// Grid x = head (fastest) for mask L2 reuse. Fuses residual: x1 = x + ctx.
// ---------------------------------------------------------------------------
#define PT 68
#define QT 128
#define KT 64
#define ATTN_SMEM ((4 * KT + QT) * PT * (int)sizeof(float))   // 104448

__global__ __launch_bounds__(256, 2)
void attn_mma_kernel(const float* __restrict__ QKV, const float* __restrict__ mask,
                     const float* __restrict__ x, float* __restrict__ x1)
{
    extern __shared__ float sm[];
    float* KsBase = sm;                   // 2 x [64][PT]
    float* VtBase = sm + 2 * KT * PT;     // 2 x [64][PT] (transposed)
    float* Ps     = sm + 4 * KT * PT;     // [128][PT]

    const int tid = threadIdx.x;
    const int w = tid >> 5, lane = tid & 31;
    const int g = lane >> 2, t = lane & 3;
    const int h = blockIdx.x, qb = blockIdx.y, b = blockIdx.z;
    const int q0 = qb * QT, hoff = h * DHH;

    const float* Kp = QKV + DD;        // K block at col 768
    const float* Vp = QKV + 2 * DD;    // V block at col 1536

    const float qscale = 0.125f * 1.4426950408889634f;  // 1/sqrt(64)*log2(e)

    // stage Q through Ps (warp-private rows), pull fragments to registers
    unsigned qf[8][4];
    {
        const int sr = tid >> 1, sc0 = (tid & 1) * 32;   // sr in [16w,16w+15]
        const float* qsrc = QKV + ((long)(b * SS + q0 + sr)) * QKVN + hoff + sc0;
        float* qdst = &Ps[sr * PT + sc0];
#pragma unroll
        for (int i = 0; i < 32; i += 4) {
            float4 v = *(const float4*)(qsrc + i);
            *(float4*)(qdst + i) = make_float4(v.x * qscale, v.y * qscale,
                                               v.z * qscale, v.w * qscale);
        }
        __syncwarp();
#pragma unroll
        for (int ks = 0; ks < 8; ks++) {
            const int rb = (w * 16 + g) * PT + ks * 8 + t;
            qf[ks][0] = __float_as_uint(Ps[rb]);
            qf[ks][1] = __float_as_uint(Ps[rb + 8 * PT]);
            qf[ks][2] = __float_as_uint(Ps[rb + 4]);
            qf[ks][3] = __float_as_uint(Ps[rb + 8 * PT + 4]);
        }
        __syncwarp();
    }

    float o[8][4];
#pragma unroll
    for (int nt = 0; nt < 8; nt++)
#pragma unroll
        for (int i = 0; i < 4; i++) o[nt][i] = 0.f;
    float m_a = -INFINITY, m_b = -INFINITY, l_a = 0.f, l_b = 0.f;

    const float* mrow_a = mask + ((long)b * SS + q0 + w * 16 + g) * SS;
    const float* mrow_b = mrow_a + 8L * SS;

    // K/V staging mapping: kr = tid>>2 (0..63), cols kc..kc+15
    const int kr = tid >> 2, kc = (tid & 3) * 16;
    const uint32_t ksbase = smem_u32(KsBase);
    const uint32_t ksoff  = (kr * PT + kc) * 4;

    // prologue: stage kb=0 into slot 0
    float4 vreg[4];
    {
        const long kv = ((long)(b * SS + kr)) * QKVN + hoff + kc;
#pragma unroll
        for (int j = 0; j < 4; j++)
            CP_ASYNC16(ksbase + ksoff + j * 16, Kp + kv + j * 4);
        CP_ASYNC_COMMIT();
#pragma unroll
        for (int j = 0; j < 4; j++)
            vreg[j] = *(const float4*)(Vp + kv + j * 4);
#pragma unroll
        for (int j = 0; j < 4; j++) {
            VtBase[(kc + j * 4 + 0) * PT + kr] = vreg[j].x;
            VtBase[(kc + j * 4 + 1) * PT + kr] = vreg[j].y;
            VtBase[(kc + j * 4 + 2) * PT + kr] = vreg[j].z;
            VtBase[(kc + j * 4 + 3) * PT + kr] = vreg[j].w;
        }
        CP_ASYNC_WAIT(0);
    }
    __syncthreads();

    const int NKB = SS / KT;   // 64
    for (int kb = 0; kb < NKB; kb++) {
        const int cur = kb & 1, nxt = cur ^ 1;
        const int k0 = kb * KT;
        const bool more = (kb + 1 < NKB);

        // prefetch next K (cp.async) and next V (registers)
        if (more) {
            const long kv = ((long)(b * SS + k0 + KT + kr)) * QKVN + hoff + kc;
            const uint32_t kd = ksbase + nxt * (KT * PT * 4) + ksoff;
#pragma unroll
            for (int j = 0; j < 4; j++)
                CP_ASYNC16(kd + j * 16, Kp + kv + j * 4);
            CP_ASYNC_COMMIT();
#pragma unroll
            for (int j = 0; j < 4; j++)
                vreg[j] = *(const float4*)(Vp + kv + j * 4);
        }

        const float* Ks = KsBase + cur * KT * PT;
        const float* Vt = VtBase + cur * KT * PT;

        // S = Q @ Ks^T (Q in registers)
        float s[8][4];
#pragma unroll
        for (int nt = 0; nt < 8; nt++)
#pragma unroll
            for (int i = 0; i < 4; i++) s[nt][i] = 0.f;
#pragma unroll
        for (int ks = 0; ks < 8; ks++) {
#pragma unroll
            for (int nt = 0; nt < 8; nt++) {
                const int cb = (nt * 8 + g) * PT + ks * 8 + t;
                unsigned b0 = __float_as_uint(Ks[cb]);
                unsigned b1 = __float_as_uint(Ks[cb + 4]);
                mma_tf32(s[nt], qf[ks][0], qf[ks][1], qf[ks][2], qf[ks][3], b0, b1);
            }
        }

        // multiplicative mask then streaming softmax (log2 domain)
        float mx_a = -INFINITY, mx_b = -INFINITY;
#pragma unroll
        for (int nt = 0; nt < 8; nt++) {
            const float2 ma = *(const float2*)(mrow_a + k0 + nt * 8 + 2 * t);
            const float2 mb = *(const float2*)(mrow_b + k0 + nt * 8 + 2 * t);
            s[nt][0] *= ma.x; s[nt][1] *= ma.y;
            s[nt][2] *= mb.x; s[nt][3] *= mb.y;
            mx_a = fmaxf(mx_a, fmaxf(s[nt][0], s[nt][1]));
            mx_b = fmaxf(mx_b, fmaxf(s[nt][2], s[nt][3]));
        }
        mx_a = fmaxf(mx_a, __shfl_xor_sync(0xffffffffu, mx_a, 1));
        mx_a = fmaxf(mx_a, __shfl_xor_sync(0xffffffffu, mx_a, 2));
        mx_b = fmaxf(mx_b, __shfl_xor_sync(0xffffffffu, mx_b, 1));
        mx_b = fmaxf(mx_b, __shfl_xor_sync(0xffffffffu, mx_b, 2));
        const float mn_a = fmaxf(m_a, mx_a), mn_b = fmaxf(m_b, mx_b);
        const float al_a = ex2(m_a - mn_a), al_b = ex2(m_b - mn_b);
        float sum_a = 0.f, sum_b = 0.f;
#pragma unroll
        for (int nt = 0; nt < 8; nt++) {
            const float p0 = ex2(s[nt][0] - mn_a);
            const float p1 = ex2(s[nt][1] - mn_a);
            const float p2 = ex2(s[nt][2] - mn_b);
            const float p3 = ex2(s[nt][3] - mn_b);
            sum_a += p0 + p1; sum_b += p2 + p3;
            const int pb = (w * 16 + g) * PT + nt * 8 + 2 * t;
            *(float2*)&Ps[pb] = make_float2(p0, p1);
            *(float2*)&Ps[pb + 8 * PT] = make_float2(p2, p3);
        }
        sum_a += __shfl_xor_sync(0xffffffffu, sum_a, 1);
        sum_a += __shfl_xor_sync(0xffffffffu, sum_a, 2);
        sum_b += __shfl_xor_sync(0xffffffffu, sum_b, 1);
        sum_b += __shfl_xor_sync(0xffffffffu, sum_b, 2);
        l_a = l_a * al_a + sum_a;
        l_b = l_b * al_b + sum_b;
        m_a = mn_a; m_b = mn_b;
#pragma unroll
        for (int nt = 0; nt < 8; nt++) {
            o[nt][0] *= al_a; o[nt][1] *= al_a;
            o[nt][2] *= al_b; o[nt][3] *= al_b;
        }
        __syncwarp();   // Ps rows are warp-private

        // O += P @ V
#pragma unroll
        for (int ks = 0; ks < 8; ks++) {
            const int rb = (w * 16 + g) * PT + ks * 8 + t;
            unsigned a0 = __float_as_uint(Ps[rb]);
            unsigned a1 = __float_as_uint(Ps[rb + 8 * PT]);
            unsigned a2 = __float_as_uint(Ps[rb + 4]);
            unsigned a3 = __float_as_uint(Ps[rb + 8 * PT + 4]);
#pragma unroll
            for (int nt = 0; nt < 8; nt++) {
                const int cb = (nt * 8 + g) * PT + ks * 8 + t;
                unsigned b0 = __float_as_uint(Vt[cb]);
                unsigned b1 = __float_as_uint(Vt[cb + 4]);
                mma_tf32(o[nt], a0, a1, a2, a3, b0, b1);
            }
        }

        // finish next-stage staging: wait K, write Vt(nxt) from registers
        if (more) {
            CP_ASYNC_WAIT(0);
            float* vt = VtBase + nxt * KT * PT;
#pragma unroll
            for (int j = 0; j < 4; j++) {
                vt[(kc + j * 4 + 0) * PT + kr] = vreg[j].x;
                vt[(kc + j * 4 + 1) * PT + kr] = vreg[j].y;
                vt[(kc + j * 4 + 2) * PT + kr] = vreg[j].z;
                vt[(kc + j * 4 + 3) * PT + kr] = vreg[j].w;
            }
        }
        __syncthreads();
    }

    // finalize + fused residual: x1 = x + O / l
    const float inv_a = 1.f / l_a, inv_b = 1.f / l_b;
    const long oa = ((long)(b * SS + q0 + w * 16 + g)) * DD + hoff;
    const long ob = oa + 8L * DD;
#pragma unroll
    for (int nt = 0; nt < 8; nt++) {
        const int c = nt * 8 + 2 * t;
        const float2 xa = *(const float2*)(x + oa + c);
        const float2 xb = *(const float2*)(x + ob + c);
        *(float2*)(x1 + oa + c) = make_float2(xa.x + o[nt][0] * inv_a,
                                              xa.y + o[nt][1] * inv_a);
        *(float2*)(x1 + ob + c) = make_float2(xb.x + o[nt][2] * inv_b,
                                              xb.y + o[nt][3] * inv_b);
    }
}

// ---------------------------------------------------------------------------
// Launch
// ---------------------------------------------------------------------------
extern "C" void kernel_launch(void* const* d_in, const int* in_sizes, int n_in,
                              void* d_out, int out_size)
{
    const float* x    = (const float*)d_in[0];
    const float* mask = (const float*)d_in[1];
    const float* wq   = (const float*)d_in[2];
    const float* bq   = (const float*)d_in[3];
    const float* wk   = (const float*)d_in[4];
    const float* bk   = (const float*)d_in[5];
    const float* wv   = (const float*)d_in[6];
    const float* bv   = (const float*)d_in[7];
    // d_in[8]=wo, d_in[9]=bo unused by the reference forward
    const float* w1   = (const float*)d_in[10];
    const float* b1   = (const float*)d_in[11];
    const float* w2   = (const float*)d_in[12];
    const float* b2   = (const float*)d_in[13];
    const float* g1   = (const float*)d_in[14];
    const float* be1  = (const float*)d_in[15];
    const float* g2   = (const float*)d_in[16];
    const float* be2  = (const float*)d_in[17];
    float* out = (float*)d_out;

    float *l1, *qkv, *x1, *l2, *hb, *wqkv, *bqkv, *w1r, *w2r;
    cudaGetSymbolAddress((void**)&l1, g_l1);
    cudaGetSymbolAddress((void**)&qkv, g_qkv);
    cudaGetSymbolAddress((void**)&x1, g_x1);
    cudaGetSymbolAddress((void**)&l2, g_l2);
    cudaGetSymbolAddress((void**)&hb, g_hb);
    cudaGetSymbolAddress((void**)&wqkv, g_wqkv);
    cudaGetSymbolAddress((void**)&bqkv, g_bqkv);
    cudaGetSymbolAddress((void**)&w1r, g_w1r);
    cudaGetSymbolAddress((void**)&w2r, g_w2r);

    cudaFuncSetAttribute(mma_gemm<1>, cudaFuncAttributeMaxDynamicSharedMemorySize, GEMM_SMEM);
    cudaFuncSetAttribute(mma_gemm<2>, cudaFuncAttributeMaxDynamicSharedMemorySize, GEMM_SMEM);
    cudaFuncSetAttribute(mma_gemm<3>, cudaFuncAttributeMaxDynamicSharedMemorySize, GEMM_SMEM);
    cudaFuncSetAttribute(attn_mma_kernel, cudaFuncAttributeMaxDynamicSharedMemorySize, ATTN_SMEM);

    // weight prep: round + concat QKV weights/biases, round w1/w2
    prep_kernel<<<(TOT4 + 255) / 256, 256>>>(wq, wk, wv, wqkv, bq, bk, bv, bqkv,
                                             w1, w1r, w2, w2r);

    // LN1 (rounds output)
    ln_kernel<<<MM, 192>>>(x, g1, be1, l1);

    // Fused QKV projection: [8192,768] @ [768,2304] -> [8192,2304]
    mma_gemm<3><<<dim3(QKVN / 128, MM / 128), 256, GEMM_SMEM>>>(
        l1, wqkv, bqkv, nullptr, qkv, MM, QKVN, DD);

    // Flash attention + residual; head = fastest grid dim for mask L2 reuse
    attn_mma_kernel<<<dim3(HH, SS / QT, BB), 256, ATTN_SMEM>>>(qkv, mask, x, x1);

    // LN2 (rounds output)
    ln_kernel<<<MM, 192>>>(x1, g2, be2, l2);

    // FFN
    mma_gemm<1><<<dim3(DFF / 128, MM / 128), 256, GEMM_SMEM>>>(l2, w1r, b1, nullptr, hb, MM, DFF, DD);
    mma_gemm<2><<<dim3(DD / 128, MM / 128), 256, GEMM_SMEM>>>(hb, w2r, b2, x1, out, MM, DD, DFF);
}

// round 8
// speedup vs baseline: 1.2348x; 1.1408x over previous
#include <cuda_runtime.h>
#include <cuda_bf16.h>
#include <cstdint>
#include <math.h>

// Problem constants
#define BB 2
#define SS 4096
#define DD 768
#define HH 12
#define DHH 64
#define DFF 3072
#define MM (BB*SS)    // 8192
#define QKVN (3*DD)   // 2304

// ---------------------------------------------------------------------------
// Scratch (device globals — allocation-free per harness rules)
// ---------------------------------------------------------------------------
__device__ float g_l1[MM*DD];
__device__ float g_qkv[MM*QKVN];     // fused Q|K|V output
__device__ float g_x1[MM*DD];
__device__ float g_l2[MM*DD];
__device__ float g_hb[MM*DFF];
__device__ float g_wqkv[DD*QKVN];    // concat rounded [768][2304]
__device__ float g_bqkv[QKVN];
__device__ float g_w1r[DD*DFF];
__device__ float g_w2r[DFF*DD];

// ---------------------------------------------------------------------------
// Helpers
// ---------------------------------------------------------------------------
__device__ __forceinline__ float f2tf32(float x) {
    unsigned r;
    asm("cvt.rna.tf32.f32 %0, %1;" : "=r"(r) : "f"(x));
    return __uint_as_float(r);
}

__device__ __forceinline__ float ex2(float x) {
    float r;
    asm("ex2.approx.f32 %0, %1;" : "=f"(r) : "f"(x));
    return r;
}

__device__ __forceinline__ uint32_t smem_u32(const void* p) {
    uint32_t a;
    asm("{ .reg .u64 t; cvta.to.shared.u64 t, %1; cvt.u32.u64 %0, t; }"
        : "=r"(a) : "l"(p));
    return a;
}

#define CP_ASYNC16(dst, src) \
    asm volatile("cp.async.cg.shared.global [%0], [%1], 16;" :: "r"((uint32_t)(dst)), "l"(src) : "memory")
#define CP_ASYNC_COMMIT() asm volatile("cp.async.commit_group;" ::: "memory")
#define CP_ASYNC_WAIT(n)  asm volatile("cp.async.wait_group %0;" :: "n"(n) : "memory")

__device__ __forceinline__ void mma_tf32(float (&d)[4],
                                         unsigned a0, unsigned a1, unsigned a2, unsigned a3,
                                         unsigned b0, unsigned b1)
{
    asm volatile(
        "mma.sync.aligned.m16n8k8.row.col.f32.tf32.tf32.f32 "
        "{%0,%1,%2,%3}, {%4,%5,%6,%7}, {%8,%9}, {%0,%1,%2,%3};\n"
        : "+f"(d[0]), "+f"(d[1]), "+f"(d[2]), "+f"(d[3])
        : "r"(a0), "r"(a1), "r"(a2), "r"(a3), "r"(b0), "r"(b1));
}

// ---------------------------------------------------------------------------
// One-pass weight prep: round wq/wk/wv into fused [768][2304], round w1, w2.
// Also concatenates biases (raw copy) into g_bqkv.
// ---------------------------------------------------------------------------
#define DD4  (DD * DD / 4)     // 147456
#define FF4  (DD * DFF / 4)    // 589824
#define TOT4 (3 * DD4 + 2 * FF4)
#define ROW4 (DD / 4)          // 192 float4 per weight row
#define QROW4 (QKVN / 4)       // 576 float4 per fused row

__global__ void prep_kernel(const float* __restrict__ wq, const float* __restrict__ wk,
                            const float* __restrict__ wv, float* __restrict__ wqkv,
                            const float* __restrict__ bq, const float* __restrict__ bk,
                            const float* __restrict__ bv, float* __restrict__ bqkv,
                            const float* __restrict__ w1, float* __restrict__ o1,
                            const float* __restrict__ w2, float* __restrict__ o2)
{
    long i = (long)blockIdx.x * blockDim.x + threadIdx.x;
    if (i >= TOT4) return;

    if (i < QROW4) {   // bias concat (raw fp32; added in fp32 epilogue)
        const float* bsrc = (i < ROW4) ? (bq + i * 4)
                          : (i < 2 * ROW4) ? (bk + (i - ROW4) * 4)
                          : (bv + (i - 2 * ROW4) * 4);
        ((float4*)bqkv)[i] = *(const float4*)bsrc;
    }

    float4 v;
    if (i < 3 * DD4) {
        const int sel   = (int)(i / DD4);          // 0=q,1=k,2=v
        const long loc  = i - (long)sel * DD4;
        const long r    = loc / ROW4;
        const long c4   = loc % ROW4;
        const float4* in = (sel == 0) ? (const float4*)wq
                         : (sel == 1) ? (const float4*)wk : (const float4*)wv;
        v = in[loc];
        ((float4*)wqkv)[r * QROW4 + sel * ROW4 + c4] =
            make_float4(f2tf32(v.x), f2tf32(v.y), f2tf32(v.z), f2tf32(v.w));
    } else if (i < 3 * DD4 + FF4) {
        const long off = i - 3 * DD4;
        v = ((const float4*)w1)[off];
        ((float4*)o1)[off] = make_float4(f2tf32(v.x), f2tf32(v.y), f2tf32(v.z), f2tf32(v.w));
    } else {
        const long off = i - 3 * DD4 - FF4;
        v = ((const float4*)w2)[off];
        ((float4*)o2)[off] = make_float4(f2tf32(v.x), f2tf32(v.y), f2tf32(v.z), f2tf32(v.w));
    }
}

// ---------------------------------------------------------------------------
// LayerNorm: torch-style, unbiased std (ddof=1), normalizer = (sigma + eps).
// 192 threads x float4. Output tf32-rounded.
// ---------------------------------------------------------------------------
__global__ void ln_kernel(const float* __restrict__ x,
                          const float* __restrict__ gamma,
                          const float* __restrict__ beta,
                          float* __restrict__ out)
{
    const int row = blockIdx.x;
    const int tid = threadIdx.x;
    const float* xr = x + (long)row * DD;

    float4 v = *(const float4*)(xr + tid * 4);
    float s  = v.x + v.y + v.z + v.w;
    float ss = v.x * v.x + v.y * v.y + v.z * v.z + v.w * v.w;
#pragma unroll
    for (int o = 16; o > 0; o >>= 1) {
        s  += __shfl_xor_sync(0xffffffffu, s,  o);
        ss += __shfl_xor_sync(0xffffffffu, ss, o);
    }
    __shared__ float sw[6], ssw[6];
    __shared__ float mu_s, inv_s;
    const int warp = tid >> 5, lane = tid & 31;
    if (lane == 0) { sw[warp] = s; ssw[warp] = ss; }
    __syncthreads();
    if (tid == 0) {
        float ts = 0.f, tss = 0.f;
#pragma unroll
        for (int i = 0; i < 6; i++) { ts += sw[i]; tss += ssw[i]; }
        float mu  = ts / 768.f;
        float var = fmaxf((tss - 768.f * mu * mu) / 767.f, 0.f);
        mu_s  = mu;
        inv_s = 1.f / (sqrtf(var) + 1e-6f);
    }
    __syncthreads();
    const float mu = mu_s, inv = inv_s;
    const float4 gm = *(const float4*)(gamma + tid * 4);
    const float4 bt = *(const float4*)(beta + tid * 4);
    *(float4*)(out + (long)row * DD + tid * 4) = make_float4(
        f2tf32(gm.x * (v.x - mu) * inv + bt.x),
        f2tf32(gm.y * (v.y - mu) * inv + bt.y),
        f2tf32(gm.z * (v.z - mu) * inv + bt.z),
        f2tf32(gm.w * (v.w - mu) * inv + bt.w));
}

// ---------------------------------------------------------------------------
// TF32 tensor-core GEMM, 4-stage cp.async pipeline (unchanged from round 7).
// ---------------------------------------------------------------------------
#define AP 20
#define BP 136
#define ASF (128 * AP)
#define BSF (16 * BP)
#define NSTG 4
#define GEMM_SMEM (NSTG * (ASF + BSF) * 4)   // 75776 B

template<int EPI>
__global__ __launch_bounds__(256, 2)
void mma_gemm(const float* __restrict__ A, const float* __restrict__ Bm,
              const float* __restrict__ bias, const float* __restrict__ res,
              float* __restrict__ C, int M, int N, int Kdim)
{
    extern __shared__ float gsm[];
    float* Asm = gsm;
    float* Bsm = gsm + NSTG * ASF;

    const int tid  = threadIdx.x;
    const int wid  = tid >> 5, lane = tid & 31;
    const int wm   = wid >> 2, wn = wid & 3;
    const int g    = lane >> 2, t = lane & 3;
    const int row0 = blockIdx.y * 128, col0 = blockIdx.x * 128;

    const int ar = tid >> 1, ac = (tid & 1) * 8;
    const int br = tid >> 4, bc = (tid & 15) * 8;

    const float* Aptr = A  + (long)(row0 + ar) * Kdim + ac;
    const float* Bptr = Bm + (long)br * N + col0 + bc;

    const uint32_t adst = smem_u32(Asm) + (ar * AP + ac) * 4;
    const uint32_t bdst = smem_u32(Bsm) + (br * BP + bc) * 4;

    float acc[4][4][4];
#pragma unroll
    for (int i = 0; i < 4; i++)
#pragma unroll
        for (int j = 0; j < 4; j++)
#pragma unroll
            for (int k = 0; k < 4; k++) acc[i][j][k] = 0.f;

    const int niter = Kdim / 16;

#pragma unroll
    for (int p = 0; p < 3; p++) {
        const long ka = (long)p * 16;
        const uint32_t ad = adst + p * (ASF * 4);
        const uint32_t bd = bdst + p * (BSF * 4);
        CP_ASYNC16(ad, Aptr + ka);
        CP_ASYNC16(ad + 16, Aptr + ka + 4);
        CP_ASYNC16(bd, Bptr + ka * N);
        CP_ASYNC16(bd + 16, Bptr + ka * N + 4);
        CP_ASYNC_COMMIT();
    }

    for (int it = 0; it < niter; it++) {
        if (it + 2 < niter)      { CP_ASYNC_WAIT(2); }
        else if (it + 1 < niter) { CP_ASYNC_WAIT(1); }
        else                     { CP_ASYNC_WAIT(0); }
        __syncthreads();

        if (it + 3 < niter) {
            const int ns = (it + 3) & (NSTG - 1);
            const long ka = (long)(it + 3) * 16;
            const uint32_t ad = adst + ns * (ASF * 4);
            const uint32_t bd = bdst + ns * (BSF * 4);
            CP_ASYNC16(ad, Aptr + ka);
            CP_ASYNC16(ad + 16, Aptr + ka + 4);
            CP_ASYNC16(bd, Bptr + ka * N);
            CP_ASYNC16(bd + 16, Bptr + ka * N + 4);
            CP_ASYNC_COMMIT();
        }

        const int slot = it & (NSTG - 1);
        const float* as = Asm + slot * ASF;
        const float* bs = Bsm + slot * BSF;
#pragma unroll
        for (int ks = 0; ks < 2; ks++) {
            unsigned af[4][4];
#pragma unroll
            for (int mt = 0; mt < 4; mt++) {
                const int rb = (wm * 64 + mt * 16 + g) * AP + ks * 8 + t;
                af[mt][0] = __float_as_uint(as[rb]);
                af[mt][1] = __float_as_uint(as[rb + 8 * AP]);
                af[mt][2] = __float_as_uint(as[rb + 4]);
                af[mt][3] = __float_as_uint(as[rb + 8 * AP + 4]);
            }
            unsigned bf[4][2];
#pragma unroll
            for (int nt = 0; nt < 4; nt++) {
                const int cb = (ks * 8 + t) * BP + wn * 32 + nt * 8 + g;
                bf[nt][0] = __float_as_uint(bs[cb]);
                bf[nt][1] = __float_as_uint(bs[cb + 4 * BP]);
            }
#pragma unroll
            for (int mt = 0; mt < 4; mt++)
#pragma unroll
                for (int nt = 0; nt < 4; nt++)
                    mma_tf32(acc[mt][nt], af[mt][0], af[mt][1], af[mt][2], af[mt][3],
                             bf[nt][0], bf[nt][1]);
        }
    }

#pragma unroll
    for (int mt = 0; mt < 4; mt++) {
#pragma unroll
        for (int nt = 0; nt < 4; nt++) {
            const int  ccol = col0 + wn * 32 + nt * 8 + 2 * t;
            const long ra   = row0 + wm * 64 + mt * 16 + g;
            const long rb2  = ra + 8;
            const float bx = bias[ccol], by = bias[ccol + 1];
            float v0 = acc[mt][nt][0] + bx;
            float v1 = acc[mt][nt][1] + by;
            float v2 = acc[mt][nt][2] + bx;
            float v3 = acc[mt][nt][3] + by;
            if (EPI == 1) {
                v0 = f2tf32(fmaxf(v0, 0.f)); v1 = f2tf32(fmaxf(v1, 0.f));
                v2 = f2tf32(fmaxf(v2, 0.f)); v3 = f2tf32(fmaxf(v3, 0.f));
            }
            if (EPI == 3) {
                v0 = f2tf32(v0); v1 = f2tf32(v1);
                v2 = f2tf32(v2); v3 = f2tf32(v3);
            }
            if (EPI == 2) {
                const float2 r0 = *(const float2*)(res + ra  * N + ccol);
                const float2 r1 = *(const float2*)(res + rb2 * N + ccol);
                v0 += r0.x; v1 += r0.y; v2 += r1.x; v3 += r1.y;
            }
            *(float2*)(C + ra  * N + ccol) = make_float2(v0, v1);
            *(float2*)(C + rb2 * N + ccol) = make_float2(v2, v3);
        }
    }
}

// ---------------------------------------------------------------------------
// Flash attention, tf32 mma.sync. Q-tile 128 rows, 128 threads = 4 warps,
// warp w owns 32 q-rows (mt=0,1 x 16) -> every K/V B-fragment feeds 2 MMAs.
// Q in registers. K-tile 32, double-buffered (K cp.async, V reg prefetch).
// Vt stores/reads XOR-swizzled -> conflict-free. 2 CTAs/SM (70.7 KB smem).
// Grid x = head (fastest) for mask L2 reuse. Fuses residual: x1 = x + ctx.
// ---------------------------------------------------------------------------
#define PT 68
#define PTV 36
#define QT 128
#define KT 32
// smem: Ks 2x[32][PT] + Vt 2x[64][PTV] + Ps [128][PT]
#define ATTN_SMEM ((2 * KT * PT + 2 * 64 * PTV + QT * PT) * (int)sizeof(float))  // 70656

__global__ __launch_bounds__(128, 2)
void attn_mma_kernel(const float* __restrict__ QKV, const float* __restrict__ mask,
                     const float* __restrict__ x, float* __restrict__ x1)
{
    extern __shared__ float sm[];
    float* KsBase = sm;                              // 2 x [32][PT]
    float* VtBase = sm + 2 * KT * PT;                // 2 x [64 dh][PTV] (transposed, swizzled)
    float* Ps     = sm + 2 * KT * PT + 2 * 64 * PTV; // [128][PT]

    const int tid = threadIdx.x;    // 0..127
    const int w = tid >> 5, lane = tid & 31;
    const int g = lane >> 2, t = lane & 3;
    const int h = blockIdx.x, qb = blockIdx.y, b = blockIdx.z;
    const int q0 = qb * QT, hoff = h * DHH;

    const float* Kp = QKV + DD;        // K block at col 768
    const float* Vp = QKV + 2 * DD;    // V block at col 1536

    const float qscale = 0.125f * 1.4426950408889634f;  // 1/sqrt(64)*log2(e)

    // stage Q through Ps (thread stages row tid -> warp-private rows 32w..32w+31),
    // then pull A-fragments for both 16-row groups into registers.
    unsigned qf[2][8][4];
    {
        const float* qsrc = QKV + ((long)(b * SS + q0 + tid)) * QKVN + hoff;
        float* qdst = &Ps[tid * PT];
#pragma unroll
        for (int i = 0; i < 64; i += 4) {
            float4 v = *(const float4*)(qsrc + i);
            *(float4*)(qdst + i) = make_float4(v.x * qscale, v.y * qscale,
                                               v.z * qscale, v.w * qscale);
        }
        __syncwarp();
#pragma unroll
        for (int mt = 0; mt < 2; mt++)
#pragma unroll
            for (int ks = 0; ks < 8; ks++) {
                const int rb = (w * 32 + mt * 16 + g) * PT + ks * 8 + t;
                qf[mt][ks][0] = __float_as_uint(Ps[rb]);
                qf[mt][ks][1] = __float_as_uint(Ps[rb + 8 * PT]);
                qf[mt][ks][2] = __float_as_uint(Ps[rb + 4]);
                qf[mt][ks][3] = __float_as_uint(Ps[rb + 8 * PT + 4]);
            }
        __syncwarp();
    }

    float o[2][8][4];
#pragma unroll
    for (int mt = 0; mt < 2; mt++)
#pragma unroll
        for (int nt = 0; nt < 8; nt++)
#pragma unroll
            for (int i = 0; i < 4; i++) o[mt][nt][i] = 0.f;
    float m_[2][2], l_[2][2];
#pragma unroll
    for (int mt = 0; mt < 2; mt++) {
        m_[mt][0] = -INFINITY; m_[mt][1] = -INFINITY;
        l_[mt][0] = 0.f;       l_[mt][1] = 0.f;
    }

    const float* mrow[2][2];
#pragma unroll
    for (int mt = 0; mt < 2; mt++) {
        const float* base = mask + ((long)b * SS + q0 + w * 32 + mt * 16 + g) * SS;
        mrow[mt][0] = base;
        mrow[mt][1] = base + 8L * SS;
    }

    // K/V staging mapping: kr = tid>>2 (0..31), cols kc..kc+15
    const int kr = tid >> 2, kc = (tid & 3) * 16;
    const uint32_t ksbase = smem_u32(KsBase);
    const uint32_t ksoff  = (kr * PT + kc) * 4;
    // Vt swizzled key index (constant per thread: dh>>4 == kc>>4 for j<16)
    const int kswz = kr ^ (8 * ((kc >> 4) & 3));

    // prologue: stage kb=0 into slot 0
    float4 vreg[4];
    {
        const long kv = ((long)(b * SS + kr)) * QKVN + hoff + kc;
#pragma unroll
        for (int j = 0; j < 4; j++)
            CP_ASYNC16(ksbase + ksoff + j * 16, Kp + kv + j * 4);
        CP_ASYNC_COMMIT();
#pragma unroll
        for (int j = 0; j < 4; j++)
            vreg[j] = *(const float4*)(Vp + kv + j * 4);
#pragma unroll
        for (int j = 0; j < 4; j++) {
            VtBase[(kc + j * 4 + 0) * PTV + kswz] = vreg[j].x;
            VtBase[(kc + j * 4 + 1) * PTV + kswz] = vreg[j].y;
            VtBase[(kc + j * 4 + 2) * PTV + kswz] = vreg[j].z;
            VtBase[(kc + j * 4 + 3) * PTV + kswz] = vreg[j].w;
        }
        CP_ASYNC_WAIT(0);
    }
    __syncthreads();

    const int NKB = SS / KT;   // 128
    for (int kb = 0; kb < NKB; kb++) {
        const int cur = kb & 1, nxt = cur ^ 1;
        const int k0 = kb * KT;
        const bool more = (kb + 1 < NKB);

        // prefetch next K (cp.async) and next V (registers)
        if (more) {
            const long kv = ((long)(b * SS + k0 + KT + kr)) * QKVN + hoff + kc;
            const uint32_t kd = ksbase + nxt * (KT * PT * 4) + ksoff;
#pragma unroll
            for (int j = 0; j < 4; j++)
                CP_ASYNC16(kd + j * 16, Kp + kv + j * 4);
            CP_ASYNC_COMMIT();
#pragma unroll
            for (int j = 0; j < 4; j++)
                vreg[j] = *(const float4*)(Vp + kv + j * 4);
        }

        const float* Ks = KsBase + cur * KT * PT;
        const float* Vt = VtBase + cur * 64 * PTV;

        // S = Q @ Ks^T : per warp 32 q-rows x 32 keys (B-frag reused x2)
        float s[2][4][4];
#pragma unroll
        for (int mt = 0; mt < 2; mt++)
#pragma unroll
            for (int nt = 0; nt < 4; nt++)
#pragma unroll
                for (int i = 0; i < 4; i++) s[mt][nt][i] = 0.f;
#pragma unroll
        for (int ks = 0; ks < 8; ks++) {
#pragma unroll
            for (int nt = 0; nt < 4; nt++) {
                const int cb = (nt * 8 + g) * PT + ks * 8 + t;
                const unsigned b0 = __float_as_uint(Ks[cb]);
                const unsigned b1 = __float_as_uint(Ks[cb + 4]);
#pragma unroll
                for (int mt = 0; mt < 2; mt++)
                    mma_tf32(s[mt][nt], qf[mt][ks][0], qf[mt][ks][1],
                             qf[mt][ks][2], qf[mt][ks][3], b0, b1);
            }
        }

        // multiplicative mask then streaming softmax (log2 domain)
#pragma unroll
        for (int mt = 0; mt < 2; mt++) {
            float mx_a = -INFINITY, mx_b = -INFINITY;
#pragma unroll
            for (int nt = 0; nt < 4; nt++) {
                const float2 ma = *(const float2*)(mrow[mt][0] + k0 + nt * 8 + 2 * t);
                const float2 mb = *(const float2*)(mrow[mt][1] + k0 + nt * 8 + 2 * t);
                s[mt][nt][0] *= ma.x; s[mt][nt][1] *= ma.y;
                s[mt][nt][2] *= mb.x; s[mt][nt][3] *= mb.y;
                mx_a = fmaxf(mx_a, fmaxf(s[mt][nt][0], s[mt][nt][1]));
                mx_b = fmaxf(mx_b, fmaxf(s[mt][nt][2], s[mt][nt][3]));
            }
            mx_a = fmaxf(mx_a, __shfl_xor_sync(0xffffffffu, mx_a, 1));
            mx_a = fmaxf(mx_a, __shfl_xor_sync(0xffffffffu, mx_a, 2));
            mx_b = fmaxf(mx_b, __shfl_xor_sync(0xffffffffu, mx_b, 1));
            mx_b = fmaxf(mx_b, __shfl_xor_sync(0xffffffffu, mx_b, 2));
            const float mn_a = fmaxf(m_[mt][0], mx_a), mn_b = fmaxf(m_[mt][1], mx_b);
            const float al_a = ex2(m_[mt][0] - mn_a), al_b = ex2(m_[mt][1] - mn_b);
            float sum_a = 0.f, sum_b = 0.f;
#pragma unroll
            for (int nt = 0; nt < 4; nt++) {
                const float p0 = ex2(s[mt][nt][0] - mn_a);
                const float p1 = ex2(s[mt][nt][1] - mn_a);
                const float p2 = ex2(s[mt][nt][2] - mn_b);
                const float p3 = ex2(s[mt][nt][3] - mn_b);
                sum_a += p0 + p1; sum_b += p2 + p3;
                const int pb = (w * 32 + mt * 16 + g) * PT + nt * 8 + 2 * t;
                *(float2*)&Ps[pb] = make_float2(p0, p1);
                *(float2*)&Ps[pb + 8 * PT] = make_float2(p2, p3);
            }
            sum_a += __shfl_xor_sync(0xffffffffu, sum_a, 1);
            sum_a += __shfl_xor_sync(0xffffffffu, sum_a, 2);
            sum_b += __shfl_xor_sync(0xffffffffu, sum_b, 1);
            sum_b += __shfl_xor_sync(0xffffffffu, sum_b, 2);
            l_[mt][0] = l_[mt][0] * al_a + sum_a;
            l_[mt][1] = l_[mt][1] * al_b + sum_b;
            m_[mt][0] = mn_a; m_[mt][1] = mn_b;
#pragma unroll
            for (int nt = 0; nt < 8; nt++) {
                o[mt][nt][0] *= al_a; o[mt][nt][1] *= al_a;
                o[mt][nt][2] *= al_b; o[mt][nt][3] *= al_b;
            }
        }
        __syncwarp();   // Ps rows are warp-private

        // O += P @ V  (32 keys -> 4 MMA k-steps; Vt B-frag reused x2)
#pragma unroll
        for (int ksv = 0; ksv < 4; ksv++) {
            unsigned af[2][4];
#pragma unroll
            for (int mt = 0; mt < 2; mt++) {
                const int rb = (w * 32 + mt * 16 + g) * PT + ksv * 8 + t;
                af[mt][0] = __float_as_uint(Ps[rb]);
                af[mt][1] = __float_as_uint(Ps[rb + 8 * PT]);
                af[mt][2] = __float_as_uint(Ps[rb + 4]);
                af[mt][3] = __float_as_uint(Ps[rb + 8 * PT + 4]);
            }
#pragma unroll
            for (int nt = 0; nt < 8; nt++) {
                const int swz = (nt >> 1) & 3;
                const int cb = (nt * 8 + g) * PTV + 8 * (ksv ^ swz) + t;
                const unsigned b0 = __float_as_uint(Vt[cb]);
                const unsigned b1 = __float_as_uint(Vt[cb + 4]);
#pragma unroll
                for (int mt = 0; mt < 2; mt++)
                    mma_tf32(o[mt][nt], af[mt][0], af[mt][1], af[mt][2], af[mt][3], b0, b1);
            }
        }

        // finish next-stage staging: wait K, write swizzled Vt(nxt)
        if (more) {
            CP_ASYNC_WAIT(0);
            float* vt = VtBase + nxt * 64 * PTV;
#pragma unroll
            for (int j = 0; j < 4; j++) {
                vt[(kc + j * 4 + 0) * PTV + kswz] = vreg[j].x;
                vt[(kc + j * 4 + 1) * PTV + kswz] = vreg[j].y;
                vt[(kc + j * 4 + 2) * PTV + kswz] = vreg[j].z;
                vt[(kc + j * 4 + 3) * PTV + kswz] = vreg[j].w;
            }
        }
        __syncthreads();
    }

    // finalize + fused residual: x1 = x + O / l
#pragma unroll
    for (int mt = 0; mt < 2; mt++) {
        const float inv_a = 1.f / l_[mt][0], inv_b = 1.f / l_[mt][1];
        const long oa = ((long)(b * SS + q0 + w * 32 + mt * 16 + g)) * DD + hoff;
        const long ob = oa + 8L * DD;
#pragma unroll
        for (int nt = 0; nt < 8; nt++) {
            const int c = nt * 8 + 2 * t;
            const float2 xa = *(const float2*)(x + oa + c);
            const float2 xb = *(const float2*)(x + ob + c);
            *(float2*)(x1 + oa + c) = make_float2(xa.x + o[mt][nt][0] * inv_a,
                                                  xa.y + o[mt][nt][1] * inv_a);
            *(float2*)(x1 + ob + c) = make_float2(xb.x + o[mt][nt][2] * inv_b,
                                                  xb.y + o[mt][nt][3] * inv_b);
        }
    }
}

// ---------------------------------------------------------------------------
// Launch
// ---------------------------------------------------------------------------
extern "C" void kernel_launch(void* const* d_in, const int* in_sizes, int n_in,
                              void* d_out, int out_size)
{
    const float* x    = (const float*)d_in[0];
    const float* mask = (const float*)d_in[1];
    const float* wq   = (const float*)d_in[2];
    const float* bq   = (const float*)d_in[3];
    const float* wk   = (const float*)d_in[4];
    const float* bk   = (const float*)d_in[5];
    const float* wv   = (const float*)d_in[6];
    const float* bv   = (const float*)d_in[7];
    // d_in[8]=wo, d_in[9]=bo unused by the reference forward
    const float* w1   = (const float*)d_in[10];
    const float* b1   = (const float*)d_in[11];
    const float* w2   = (const float*)d_in[12];
    const float* b2   = (const float*)d_in[13];
    const float* g1   = (const float*)d_in[14];
    const float* be1  = (const float*)d_in[15];
    const float* g2   = (const float*)d_in[16];
    const float* be2  = (const float*)d_in[17];
    float* out = (float*)d_out;

    float *l1, *qkv, *x1, *l2, *hb, *wqkv, *bqkv, *w1r, *w2r;
    cudaGetSymbolAddress((void**)&l1, g_l1);
    cudaGetSymbolAddress((void**)&qkv, g_qkv);
    cudaGetSymbolAddress((void**)&x1, g_x1);
    cudaGetSymbolAddress((void**)&l2, g_l2);
    cudaGetSymbolAddress((void**)&hb, g_hb);
    cudaGetSymbolAddress((void**)&wqkv, g_wqkv);
    cudaGetSymbolAddress((void**)&bqkv, g_bqkv);
    cudaGetSymbolAddress((void**)&w1r, g_w1r);
    cudaGetSymbolAddress((void**)&w2r, g_w2r);

    cudaFuncSetAttribute(mma_gemm<1>, cudaFuncAttributeMaxDynamicSharedMemorySize, GEMM_SMEM);
    cudaFuncSetAttribute(mma_gemm<2>, cudaFuncAttributeMaxDynamicSharedMemorySize, GEMM_SMEM);
    cudaFuncSetAttribute(mma_gemm<3>, cudaFuncAttributeMaxDynamicSharedMemorySize, GEMM_SMEM);
    cudaFuncSetAttribute(attn_mma_kernel, cudaFuncAttributeMaxDynamicSharedMemorySize, ATTN_SMEM);

    // weight prep: round + concat QKV weights/biases, round w1/w2
    prep_kernel<<<(TOT4 + 255) / 256, 256>>>(wq, wk, wv, wqkv, bq, bk, bv, bqkv,
                                             w1, w1r, w2, w2r);

    // LN1 (rounds output)
    ln_kernel<<<MM, 192>>>(x, g1, be1, l1);

    // Fused QKV projection: [8192,768] @ [768,2304] -> [8192,2304]
    mma_gemm<3><<<dim3(QKVN / 128, MM / 128), 256, GEMM_SMEM>>>(
        l1, wqkv, bqkv, nullptr, qkv, MM, QKVN, DD);

    // Flash attention + residual; head = fastest grid dim for mask L2 reuse
    attn_mma_kernel<<<dim3(HH, SS / QT, BB), 128, ATTN_SMEM>>>(qkv, mask, x, x1);

    // LN2 (rounds output)
    ln_kernel<<<MM, 192>>>(x1, g2, be2, l2);

    // FFN
    mma_gemm<1><<<dim3(DFF / 128, MM / 128), 256, GEMM_SMEM>>>(l2, w1r, b1, nullptr, hb, MM, DFF, DD);
    mma_gemm<2><<<dim3(DD / 128, MM / 128), 256, GEMM_SMEM>>>(hb, w2r, b2, x1, out, MM, DD, DFF);
}